// round 13
// baseline (speedup 1.0000x reference)
#include <cuda_runtime.h>
#include <cuda_fp16.h>
#include <stdint.h>
#include <math.h>

// Problem constants
#define T_TOK 4096
#define H_DIM 1024
#define I_DIM 2048
#define N_EXP 8

// ---------------- scratch (static device globals; no allocs) ----------------
__device__ int    g_cnt[N_EXP];
__device__ int    g_tok[N_EXP][T_TOK];
__device__ float  g_wt [N_EXP][T_TOK];
__device__ int    g_slot[N_EXP][T_TOK];                  // output slot = 2*t + rank
__device__ __half g_hidden[(size_t)2 * T_TOK * I_DIM];   // routed SwiGLU hidden
__device__ float  g_eout [(size_t)2 * T_TOK * H_DIM];    // routed expert out
__device__ __half g_shid [(size_t)T_TOK * I_DIM];        // shared hidden
__device__ float  g_shout[(size_t)T_TOK * H_DIM];        // shared out
__device__ float  g_zsq[T_TOK];

// fp16 copies (pre-converted once per launch)
__device__ __half g_xh  [(size_t)T_TOK * H_DIM];
__device__ __half g_xsh [(size_t)T_TOK * H_DIM];
__device__ __half g_hWg [(size_t)N_EXP * I_DIM * H_DIM];
__device__ __half g_hWu [(size_t)N_EXP * I_DIM * H_DIM];
__device__ __half g_hWd [(size_t)N_EXP * H_DIM * I_DIM];
__device__ __half g_hsWg[(size_t)I_DIM * H_DIM];
__device__ __half g_hsWu[(size_t)I_DIM * H_DIM];
__device__ __half g_hsWd[(size_t)H_DIM * I_DIM];

__device__ __forceinline__ uint32_t h2u(half2 h) { return *(uint32_t*)&h; }
__device__ __forceinline__ uint32_t smem_u32(const void* p) {
    return (uint32_t)__cvta_generic_to_shared(p);
}
__device__ __forceinline__ uint4 cvt8(float4 a, float4 b) {
    uint4 r;
    r.x = h2u(__floats2half2_rn(a.x, a.y));
    r.y = h2u(__floats2half2_rn(a.z, a.w));
    r.z = h2u(__floats2half2_rn(b.x, b.y));
    r.w = h2u(__floats2half2_rn(b.z, b.w));
    return r;
}

// group counts (8 fp32 elems per group)
#define GW  (N_EXP * I_DIM * H_DIM / 8)      // 2097152
#define GS  (I_DIM * H_DIM / 8)              // 262144
#define NWTOT (3u * GW + 3u * GS)            // 7077888 weight groups

// ---------------- zero counters ----------------
__global__ void zero_cnt_kernel() {
    if (threadIdx.x < N_EXP) g_cnt[threadIdx.x] = 0;
}

// ---------------- router (+ fused fp32->fp16 conversion) ----------------
__global__ void __launch_bounds__(256) router_kernel(
    const float* __restrict__ x,
    const float* __restrict__ ln_g, const float* __restrict__ ln_b,
    const float* __restrict__ gate_w, const float* __restrict__ bias,
    const float* __restrict__ sh_g, const float* __restrict__ sh_b,
    const float* __restrict__ Wg, const float* __restrict__ Wu,
    const float* __restrict__ Wd,
    const float* __restrict__ sWg, const float* __restrict__ sWu,
    const float* __restrict__ sWd)
{
    __shared__ float sx[H_DIM];
    __shared__ float sred[8], sred2[8];
    __shared__ float s_mean, s_rstd;
    __shared__ float logits[N_EXP];

    const int t   = blockIdx.x;
    const int tid = threadIdx.x;
    const float* xr = x + (size_t)t * H_DIM;

    float s = 0.f, s2 = 0.f;
#pragma unroll
    for (int i = 0; i < H_DIM / 256; i++) {
        float v = xr[tid + i * 256];
        sx[tid + i * 256] = v;
        s += v; s2 += v * v;
    }
#pragma unroll
    for (int o = 16; o; o >>= 1) {
        s  += __shfl_xor_sync(0xffffffffu, s,  o);
        s2 += __shfl_xor_sync(0xffffffffu, s2, o);
    }
    const int wid = tid >> 5, lane = tid & 31;
    if (lane == 0) { sred[wid] = s; sred2[wid] = s2; }
    __syncthreads();
    if (tid == 0) {
        float a = 0.f, b = 0.f;
        for (int i = 0; i < 8; i++) { a += sred[i]; b += sred2[i]; }
        float mean = a * (1.f / H_DIM);
        float var  = b * (1.f / H_DIM) - mean * mean;
        s_mean = mean;
        s_rstd = rsqrtf(var + 1e-5f);
    }
    __syncthreads();
    const float mean = s_mean, rstd = s_rstd;

    {
        const float* gw = gate_w + wid * H_DIM;
        float acc = 0.f;
        for (int i = lane; i < H_DIM; i += 32) {
            float hn = (sx[i] - mean) * rstd * ln_g[i] + ln_b[i];
            acc += hn * gw[i];
        }
#pragma unroll
        for (int o = 16; o; o >>= 1) acc += __shfl_xor_sync(0xffffffffu, acc, o);
        if (lane == 0) logits[wid] = acc + bias[wid];
    }

    // x -> half, shared-expert LN -> half (from smem copy, free)
#pragma unroll
    for (int i = 0; i < H_DIM / 256; i++) {
        int idx = tid + i * 256;
        float v = sx[idx];
        g_xh [(size_t)t * H_DIM + idx] = __float2half_rn(v);
        float vn = (v - mean) * rstd * sh_g[idx] + sh_b[idx];
        g_xsh[(size_t)t * H_DIM + idx] = __float2half_rn(vn);
    }
    __syncthreads();

    if (tid == 0) {
        float mx = logits[0];
#pragma unroll
        for (int e = 1; e < N_EXP; e++) mx = fmaxf(mx, logits[e]);
        float p[N_EXP]; float se = 0.f;
#pragma unroll
        for (int e = 0; e < N_EXP; e++) { p[e] = expf(logits[e] - mx); se += p[e]; }
        float z = mx + logf(se);
        g_zsq[t] = z * z;
        int e1 = 0;
#pragma unroll
        for (int e = 1; e < N_EXP; e++) if (p[e] > p[e1]) e1 = e;
        int e2 = (e1 == 0) ? 1 : 0;
#pragma unroll
        for (int e = 0; e < N_EXP; e++) if (e != e1 && p[e] > p[e2]) e2 = e;
        float inv = 1.f / se;
        float p1 = p[e1] * inv, p2 = p[e2] * inv;
        float sm = fmaxf(p1 + p2, 1e-5f);
        int pos = atomicAdd(&g_cnt[e1], 1);
        g_tok[e1][pos] = t; g_wt[e1][pos] = p1 / sm; g_slot[e1][pos] = 2 * t;
        pos = atomicAdd(&g_cnt[e2], 1);
        g_tok[e2][pos] = t; g_wt[e2][pos] = p2 / sm; g_slot[e2][pos] = 2 * t + 1;
    }

    // fused weight conversion (grid-stride over all 6 weight tensors)
    for (unsigned i = blockIdx.x * 256u + tid; i < NWTOT; i += 4096u * 256u) {
        const float* sp; __half* d; unsigned off;
        if (i < GW)               { sp = Wg;  d = g_hWg;  off = i; }
        else if (i < 2u*GW)       { sp = Wu;  d = g_hWu;  off = i - GW; }
        else if (i < 3u*GW)       { sp = Wd;  d = g_hWd;  off = i - 2u*GW; }
        else if (i < 3u*GW + GS)  { sp = sWg; d = g_hsWg; off = i - 3u*GW; }
        else if (i < 3u*GW + 2u*GS) { sp = sWu; d = g_hsWu; off = i - 3u*GW - GS; }
        else                      { sp = sWd; d = g_hsWd; off = i - 3u*GW - 2u*GS; }
        float4 a = ((const float4*)sp)[2 * (size_t)off];
        float4 b = ((const float4*)sp)[2 * (size_t)off + 1];
        ((uint4*)d)[off] = cvt8(a, b);
    }
}

// ===== HMMA GEMMs: 128x128 block, 8 warps of 32x64, BK=32, pitch64+XOR =====
#define BM 128
#define BK 32
#define NSTAGE 6
#define TILE_BYTES 8192                // 128 rows x 64B, XOR-swizzled
#define B_OFF TILE_BYTES
#define STAGE_BYTES (2 * TILE_BYTES)   // 16384
#define SMEM_DYN (NSTAGE * STAGE_BYTES + 1024)

#define MMA16816(d, a, b) \
  asm volatile("mma.sync.aligned.m16n8k16.row.col.f32.f16.f16.f32 " \
    "{%0,%1,%2,%3}, {%4,%5,%6,%7}, {%8,%9}, {%0,%1,%2,%3};" \
    : "+f"((d)[0]), "+f"((d)[1]), "+f"((d)[2]), "+f"((d)[3]) \
    : "r"((a)[0]), "r"((a)[1]), "r"((a)[2]), "r"((a)[3]), "r"((b)[0]), "r"((b)[1]))

#define LDSM4(r0, r1, r2, r3, addr) \
  asm volatile("ldmatrix.sync.aligned.m8n8.x4.shared.b16 {%0,%1,%2,%3}, [%4];" \
    : "=r"(r0), "=r"(r1), "=r"(r2), "=r"(r3) : "r"(addr))

#define CPA16(dst, src, sz) \
  asm volatile("cp.async.cg.shared.global [%0], [%1], 16, %2;" \
    :: "r"(dst), "l"(src), "r"(sz))
#define CPCOMMIT() asm volatile("cp.async.commit_group;")
#define CPWAIT(n)  asm volatile("cp.async.wait_group %0;" :: "n"(n))

// swizzle: byte addr of (row, seg) = row*64 + ((seg ^ ((row>>1)&3)) * 16)
// -> (addr>>4)&7 = (4*row + seg^rx2) mod 8: conflict-free for 8-row phases
//    and for 32-consecutive-row cp.async stores. Row offsets that are
//    multiples of 8 leave (row>>1)&3 invariant, so per-lane constants hoist.

// fused gate/up GEMM + SwiGLU.  z: 0..7 routed, 8 = shared.
__global__ void __launch_bounds__(256, 2) hm_gateup(
    const __half* __restrict__ xh,  const __half* __restrict__ xsh,
    const __half* __restrict__ Wg_all, const __half* __restrict__ Wu_all,
    const __half* __restrict__ sWg, const __half* __restrict__ sWu)
{
    extern __shared__ uint8_t dsm[];
    const int e = blockIdx.z;
    const bool se = (e == N_EXP);
    const int cnt = se ? T_TOK : g_cnt[e];
    const int m0 = blockIdx.x * BM;
    if (m0 >= cnt) return;
    const int n0 = blockIdx.y * 64;

    const __half* xp = se ? xsh : xh;
    const __half* wg = se ? sWg : Wg_all + (size_t)e * I_DIM * H_DIM;
    const __half* wu = se ? sWu : Wu_all + (size_t)e * I_DIM * H_DIM;
    __half* hid = se ? g_shid : g_hidden;

    const int tid  = threadIdx.x;
    const int lane = tid & 31;
    const int wid  = tid >> 5;
    const int wm   = (wid & 3) * 32;
    const int wn   = (wid >> 2) * 64;
    const int fr   = lane >> 2;
    const int fc   = lane & 3;

    // loader maps
    const int arow = tid & 127;
    const int ah   = (tid >> 7) * 2;          // seg base {0,2}
    const int rxs  = (arow & 7) >> 1;         // (row>>1)&3
    const __half* aptr = xp;
    uint32_t asz = 0;
    if (m0 + arow < cnt) {
        int r = se ? (m0 + arow) : g_tok[e][m0 + arow];
        aptr = xp + (size_t)r * H_DIM;
        asz = 16u;
    }
    const int brow = arow;
    const __half* bbase = (brow & 32) ? wu : wg;
    const __half* bptr = bbase + (size_t)(n0 + ((brow >> 6) << 5) + (brow & 31)) * H_DIM;

    const uint32_t sb = (smem_u32(dsm) + 1023) & ~1023u;
    const uint32_t a0 = arow * 64 + ((ah ^ rxs) * 16);
    const uint32_t a1 = arow * 64 + (((ah + 1) ^ rxs) * 16);
    const uint32_t b0 = B_OFF + a0;
    const uint32_t b1 = B_OFF + a1;

    // fragment lane offsets (per s-slice, fully hoisted)
    const int lrow = (lane & 7) + ((lane >> 3) & 1) * 8;
    const int lrx  = (lane & 7) >> 1;
    const int lcs  = (lane >> 4) & 1;
    const uint32_t loff0 = (uint32_t)(lrow * 64 + ((lcs ^ lrx) * 16));
    const uint32_t loff1 = (uint32_t)(lrow * 64 + (((2 + lcs) ^ lrx) * 16));

    float acc[2][8][4] = {};
    const int NCH = H_DIM / BK;   // 32

#define GU_ISSUE(c, SLOT) do { \
    uint32_t st_ = sb + (uint32_t)(SLOT) * STAGE_BYTES; \
    const __half* a_ = aptr + (c) * BK + ah * 8; \
    const __half* b_ = bptr + (c) * BK + ah * 8; \
    CPA16(st_ + a0, a_,     asz); \
    CPA16(st_ + a1, a_ + 8, asz); \
    CPA16(st_ + b0, b_,     16u); \
    CPA16(st_ + b1, b_ + 8, 16u); \
} while (0)

#define GU_COMP(SLOT) do { \
    const uint32_t stb_ = sb + (uint32_t)(SLOT) * STAGE_BYTES; \
    _Pragma("unroll") \
    for (int s = 0; s < 2; s++) { \
        const uint32_t lo = s ? loff1 : loff0; \
        const uint32_t Ab_ = stb_ + lo + wm * 64; \
        const uint32_t Bb_ = stb_ + B_OFF + lo + wn * 64; \
        uint32_t a[2][4]; uint32_t b[8][2]; \
        LDSM4(a[0][0], a[0][1], a[0][2], a[0][3], Ab_); \
        LDSM4(a[1][0], a[1][1], a[1][2], a[1][3], Ab_ + 1024); \
        { uint32_t q0, q1, q2, q3; \
          LDSM4(q0, q1, q2, q3, Bb_); \
          b[0][0] = q0; b[0][1] = q2; b[1][0] = q1; b[1][1] = q3; \
          LDSM4(q0, q1, q2, q3, Bb_ + 1024); \
          b[2][0] = q0; b[2][1] = q2; b[3][0] = q1; b[3][1] = q3; } \
        _Pragma("unroll") \
        for (int mt = 0; mt < 2; mt++) \
            _Pragma("unroll") \
            for (int nt = 0; nt < 4; nt++) \
                MMA16816(acc[mt][nt], a[mt], b[nt]); \
        { uint32_t q0, q1, q2, q3; \
          LDSM4(q0, q1, q2, q3, Bb_ + 2048); \
          b[4][0] = q0; b[4][1] = q2; b[5][0] = q1; b[5][1] = q3; \
          LDSM4(q0, q1, q2, q3, Bb_ + 3072); \
          b[6][0] = q0; b[6][1] = q2; b[7][0] = q1; b[7][1] = q3; } \
        _Pragma("unroll") \
        for (int mt = 0; mt < 2; mt++) \
            _Pragma("unroll") \
            for (int nt = 4; nt < 8; nt++) \
                MMA16816(acc[mt][nt], a[mt], b[nt]); \
    } \
} while (0)

    GU_ISSUE(0, 0); CPCOMMIT();
    GU_ISSUE(1, 1); CPCOMMIT();
    GU_ISSUE(2, 2); CPCOMMIT();
    GU_ISSUE(3, 3); CPCOMMIT();

    int sl = 0;    // slot of chunk c; pairs -> sl in {0,2,4}
    for (int c = 0; c < NCH; c += 2) {
        CPWAIT(2);
        __syncthreads();
        int s1 = sl + 4; if (s1 >= NSTAGE) s1 -= NSTAGE;
        int s2 = sl + 5; if (s2 >= NSTAGE) s2 -= NSTAGE;
        if (c + 4 < NCH) GU_ISSUE(c + 4, s1);
        CPCOMMIT();
        if (c + 5 < NCH) GU_ISSUE(c + 5, s2);
        CPCOMMIT();
        GU_COMP(sl);
        GU_COMP(sl + 1);
        sl += 2; if (sl >= NSTAGE) sl = 0;
    }

    // epilogue: silu(gate)*up; nt 0..3 gate, 4..7 matching up
    const int colbase = n0 + (wn >> 1);
#pragma unroll
    for (int mt = 0; mt < 2; mt++) {
#pragma unroll
        for (int i2 = 0; i2 < 2; i2++) {
            int row = wm + mt * 16 + fr + i2 * 8;
            int m = m0 + row;
            if (m >= cnt) continue;
            int orow = se ? m : g_slot[e][m];
            __half* op = hid + (size_t)orow * I_DIM + colbase;
#pragma unroll
            for (int j = 0; j < 4; j++) {
                float g0 = acc[mt][j][i2*2+0],   g1 = acc[mt][j][i2*2+1];
                float u0 = acc[mt][4+j][i2*2+0], u1 = acc[mt][4+j][i2*2+1];
                float v0 = (g0 / (1.f + expf(-g0))) * u0;
                float v1 = (g1 / (1.f + expf(-g1))) * u1;
                *(half2*)(op + j * 8 + 2 * fc) = __floats2half2_rn(v0, v1);
            }
        }
    }
}

// down GEMM (+ combine weight for routed). 128 H-cols per block.
__global__ void __launch_bounds__(256, 2) hm_down(
    const __half* __restrict__ Wd_all, const __half* __restrict__ sWd)
{
    extern __shared__ uint8_t dsm[];
    const int e = blockIdx.z;
    const bool se = (e == N_EXP);
    const int cnt = se ? T_TOK : g_cnt[e];
    const int m0 = blockIdx.x * BM;
    if (m0 >= cnt) return;
    const int n0 = blockIdx.y * 128;

    const __half* hid = se ? g_shid : g_hidden;
    const __half* wd  = se ? sWd : Wd_all + (size_t)e * H_DIM * I_DIM;

    const int tid  = threadIdx.x;
    const int lane = tid & 31;
    const int wid  = tid >> 5;
    const int wm   = (wid & 3) * 32;
    const int wn   = (wid >> 2) * 64;
    const int fr   = lane >> 2;
    const int fc   = lane & 3;

    const int arow = tid & 127;
    const int ah   = (tid >> 7) * 2;
    const int rxs  = (arow & 7) >> 1;
    const __half* aptr = hid;
    uint32_t asz = 0;
    if (m0 + arow < cnt) {
        int slot = se ? (m0 + arow) : g_slot[e][m0 + arow];
        aptr = hid + (size_t)slot * I_DIM;
        asz = 16u;
    }
    const __half* bptr = wd + (size_t)(n0 + arow) * I_DIM;

    const uint32_t sb = (smem_u32(dsm) + 1023) & ~1023u;
    const uint32_t a0 = arow * 64 + ((ah ^ rxs) * 16);
    const uint32_t a1 = arow * 64 + (((ah + 1) ^ rxs) * 16);
    const uint32_t b0 = B_OFF + a0;
    const uint32_t b1 = B_OFF + a1;

    const int lrow = (lane & 7) + ((lane >> 3) & 1) * 8;
    const int lrx  = (lane & 7) >> 1;
    const int lcs  = (lane >> 4) & 1;
    const uint32_t loff0 = (uint32_t)(lrow * 64 + ((lcs ^ lrx) * 16));
    const uint32_t loff1 = (uint32_t)(lrow * 64 + (((2 + lcs) ^ lrx) * 16));

    float acc[2][8][4] = {};
    const int NCH = I_DIM / BK;   // 64

#define DN_ISSUE(c, SLOT) do { \
    uint32_t st_ = sb + (uint32_t)(SLOT) * STAGE_BYTES; \
    const __half* a_ = aptr + (c) * BK + ah * 8; \
    const __half* b_ = bptr + (c) * BK + ah * 8; \
    CPA16(st_ + a0, a_,     asz); \
    CPA16(st_ + a1, a_ + 8, asz); \
    CPA16(st_ + b0, b_,     16u); \
    CPA16(st_ + b1, b_ + 8, 16u); \
} while (0)

#define DN_COMP(SLOT) do { \
    const uint32_t stb_ = sb + (uint32_t)(SLOT) * STAGE_BYTES; \
    _Pragma("unroll") \
    for (int s = 0; s < 2; s++) { \
        const uint32_t lo = s ? loff1 : loff0; \
        const uint32_t Ab_ = stb_ + lo + wm * 64; \
        const uint32_t Bb_ = stb_ + B_OFF + lo + wn * 64; \
        uint32_t a[2][4]; uint32_t b[8][2]; \
        LDSM4(a[0][0], a[0][1], a[0][2], a[0][3], Ab_); \
        LDSM4(a[1][0], a[1][1], a[1][2], a[1][3], Ab_ + 1024); \
        { uint32_t q0, q1, q2, q3; \
          LDSM4(q0, q1, q2, q3, Bb_); \
          b[0][0] = q0; b[0][1] = q2; b[1][0] = q1; b[1][1] = q3; \
          LDSM4(q0, q1, q2, q3, Bb_ + 1024); \
          b[2][0] = q0; b[2][1] = q2; b[3][0] = q1; b[3][1] = q3; } \
        _Pragma("unroll") \
        for (int mt = 0; mt < 2; mt++) \
            _Pragma("unroll") \
            for (int nt = 0; nt < 4; nt++) \
                MMA16816(acc[mt][nt], a[mt], b[nt]); \
        { uint32_t q0, q1, q2, q3; \
          LDSM4(q0, q1, q2, q3, Bb_ + 2048); \
          b[4][0] = q0; b[4][1] = q2; b[5][0] = q1; b[5][1] = q3; \
          LDSM4(q0, q1, q2, q3, Bb_ + 3072); \
          b[6][0] = q0; b[6][1] = q2; b[7][0] = q1; b[7][1] = q3; } \
        _Pragma("unroll") \
        for (int mt = 0; mt < 2; mt++) \
            _Pragma("unroll") \
            for (int nt = 4; nt < 8; nt++) \
                MMA16816(acc[mt][nt], a[mt], b[nt]); \
    } \
} while (0)

    DN_ISSUE(0, 0); CPCOMMIT();
    DN_ISSUE(1, 1); CPCOMMIT();
    DN_ISSUE(2, 2); CPCOMMIT();
    DN_ISSUE(3, 3); CPCOMMIT();

    int sl = 0;
    for (int c = 0; c < NCH; c += 2) {
        CPWAIT(2);
        __syncthreads();
        int s1 = sl + 4; if (s1 >= NSTAGE) s1 -= NSTAGE;
        int s2 = sl + 5; if (s2 >= NSTAGE) s2 -= NSTAGE;
        if (c + 4 < NCH) DN_ISSUE(c + 4, s1);
        CPCOMMIT();
        if (c + 5 < NCH) DN_ISSUE(c + 5, s2);
        CPCOMMIT();
        DN_COMP(sl);
        DN_COMP(sl + 1);
        sl += 2; if (sl >= NSTAGE) sl = 0;
    }

#pragma unroll
    for (int mt = 0; mt < 2; mt++) {
#pragma unroll
        for (int i2 = 0; i2 < 2; i2++) {
            int row = wm + mt * 16 + fr + i2 * 8;
            int m = m0 + row;
            if (m >= cnt) continue;
            if (se) {
                float* op = g_shout + (size_t)m * H_DIM + n0 + wn;
#pragma unroll
                for (int nt = 0; nt < 8; nt++) {
                    float2 v;
                    v.x = acc[mt][nt][i2*2+0];
                    v.y = acc[mt][nt][i2*2+1];
                    *(float2*)(op + nt * 8 + 2 * fc) = v;
                }
            } else {
                int orow = g_slot[e][m];
                float w  = g_wt[e][m];
                float* op = g_eout + (size_t)orow * H_DIM + n0 + wn;
#pragma unroll
                for (int nt = 0; nt < 8; nt++) {
                    float2 v;
                    v.x = acc[mt][nt][i2*2+0] * w;
                    v.y = acc[mt][nt][i2*2+1] * w;
                    *(float2*)(op + nt * 8 + 2 * fc) = v;
                }
            }
        }
    }
}

// ---------------- combine ----------------
__global__ void __launch_bounds__(256) combine_kernel(
    float* __restrict__ out, const float* __restrict__ shared_gate)
{
    const int idx = blockIdx.x * 256 + threadIdx.x;
    const float sig = 1.f / (1.f + expf(-shared_gate[0]));
    const int t = idx >> 10;
    const int h = idx & (H_DIM - 1);
    out[idx] = g_eout[(size_t)(2 * t) * H_DIM + h]
             + g_eout[(size_t)(2 * t + 1) * H_DIM + h]
             + g_shout[idx] * sig;
}

// ---------------- aux z-loss ----------------
__global__ void __launch_bounds__(256) aux_kernel(float* __restrict__ out)
{
    __shared__ float red[256];
    const int tid = threadIdx.x;
    float s = 0.f;
    for (int i = tid; i < T_TOK; i += 256) s += g_zsq[i];
    red[tid] = s;
    __syncthreads();
    for (int o = 128; o; o >>= 1) {
        if (tid < o) red[tid] += red[tid + o];
        __syncthreads();
    }
    if (tid == 0) out[(size_t)T_TOK * H_DIM] = red[0] * (1e-4f / T_TOK);
}

// ---------------- launch ----------------
extern "C" void kernel_launch(void* const* d_in, const int* in_sizes, int n_in,
                              void* d_out, int out_size)
{
    const float* x      = (const float*)d_in[0];
    const float* ln_g   = (const float*)d_in[1];
    const float* ln_b   = (const float*)d_in[2];
    const float* gate_w = (const float*)d_in[3];
    const float* bias   = (const float*)d_in[4];
    const float* Wg     = (const float*)d_in[5];
    const float* Wu     = (const float*)d_in[6];
    const float* Wd     = (const float*)d_in[7];
    const float* sh_g   = (const float*)d_in[8];
    const float* sh_b   = (const float*)d_in[9];
    const float* sWg    = (const float*)d_in[10];
    const float* sWu    = (const float*)d_in[11];
    const float* sWd    = (const float*)d_in[12];
    const float* sgate  = (const float*)d_in[13];
    float* out = (float*)d_out;

    static int attr_done = 0;
    if (!attr_done) {
        cudaFuncSetAttribute(hm_gateup,
            cudaFuncAttributeMaxDynamicSharedMemorySize, SMEM_DYN);
        cudaFuncSetAttribute(hm_down,
            cudaFuncAttributeMaxDynamicSharedMemorySize, SMEM_DYN);
        attr_done = 1;
    }

    __half *xh, *xsh;
    cudaGetSymbolAddress((void**)&xh,  g_xh);
    cudaGetSymbolAddress((void**)&xsh, g_xsh);
    __half *hWg, *hWu, *hWd, *hsWg, *hsWu, *hsWd;
    cudaGetSymbolAddress((void**)&hWg, g_hWg);
    cudaGetSymbolAddress((void**)&hWu, g_hWu);
    cudaGetSymbolAddress((void**)&hWd, g_hWd);
    cudaGetSymbolAddress((void**)&hsWg, g_hsWg);
    cudaGetSymbolAddress((void**)&hsWu, g_hsWu);
    cudaGetSymbolAddress((void**)&hsWd, g_hsWd);

    zero_cnt_kernel<<<1, 32>>>();                                           // 1
    router_kernel<<<T_TOK, 256>>>(x, ln_g, ln_b, gate_w, bias, sh_g, sh_b,
                                  Wg, Wu, Wd, sWg, sWu, sWd);               // 2

    dim3 gu_grid(T_TOK / BM, I_DIM / 64, N_EXP + 1);
    hm_gateup<<<gu_grid, 256, SMEM_DYN>>>(xh, xsh, hWg, hWu, hsWg, hsWu);   // 3

    dim3 dn_grid(T_TOK / BM, H_DIM / 128, N_EXP + 1);
    hm_down<<<dn_grid, 256, SMEM_DYN>>>(hWd, hsWd);                         // 4 (profiled)

    combine_kernel<<<(T_TOK * H_DIM) / 256, 256>>>(out, sgate);             // 5
    aux_kernel<<<1, 256>>>(out);                                            // 6
}

// round 14
// speedup vs baseline: 1.0654x; 1.0654x over previous
#include <cuda_runtime.h>
#include <cuda_fp16.h>
#include <stdint.h>
#include <math.h>

// Problem constants
#define T_TOK 4096
#define H_DIM 1024
#define I_DIM 2048
#define N_EXP 8

// ---------------- scratch (static device globals; no allocs) ----------------
__device__ int    g_cnt[N_EXP];
__device__ int    g_tok[N_EXP][T_TOK];
__device__ float  g_wt [N_EXP][T_TOK];
__device__ int    g_slot[N_EXP][T_TOK];                  // output slot = 2*t + rank
__device__ __half g_hidden[(size_t)2 * T_TOK * I_DIM];   // routed SwiGLU hidden
__device__ float  g_eout [(size_t)2 * T_TOK * H_DIM];    // routed expert out
__device__ __half g_shid [(size_t)T_TOK * I_DIM];        // shared hidden
__device__ float  g_shout[(size_t)T_TOK * H_DIM];        // shared out
__device__ float  g_zsq[T_TOK];

// fp16 copies (pre-converted once per launch)
__device__ __half g_xh  [(size_t)T_TOK * H_DIM];
__device__ __half g_xsh [(size_t)T_TOK * H_DIM];
__device__ __half g_hWg [(size_t)N_EXP * I_DIM * H_DIM];
__device__ __half g_hWu [(size_t)N_EXP * I_DIM * H_DIM];
__device__ __half g_hWd [(size_t)N_EXP * H_DIM * I_DIM];
__device__ __half g_hsWg[(size_t)I_DIM * H_DIM];
__device__ __half g_hsWu[(size_t)I_DIM * H_DIM];
__device__ __half g_hsWd[(size_t)H_DIM * I_DIM];

__device__ __forceinline__ uint32_t h2u(half2 h) { return *(uint32_t*)&h; }
__device__ __forceinline__ uint32_t smem_u32(const void* p) {
    return (uint32_t)__cvta_generic_to_shared(p);
}
__device__ __forceinline__ uint4 cvt8(float4 a, float4 b) {
    uint4 r;
    r.x = h2u(__floats2half2_rn(a.x, a.y));
    r.y = h2u(__floats2half2_rn(a.z, a.w));
    r.z = h2u(__floats2half2_rn(b.x, b.y));
    r.w = h2u(__floats2half2_rn(b.z, b.w));
    return r;
}

// group counts (8 fp32 elems per group)
#define GW  (N_EXP * I_DIM * H_DIM / 8)      // 2097152
#define GS  (I_DIM * H_DIM / 8)              // 262144
#define NWTOT (3u * GW + 3u * GS)            // 7077888 weight groups

// ---------------- zero counters ----------------
__global__ void zero_cnt_kernel() {
    if (threadIdx.x < N_EXP) g_cnt[threadIdx.x] = 0;
}

// ---------------- router (+ fused fp32->fp16 conversion) ----------------
__global__ void __launch_bounds__(256) router_kernel(
    const float* __restrict__ x,
    const float* __restrict__ ln_g, const float* __restrict__ ln_b,
    const float* __restrict__ gate_w, const float* __restrict__ bias,
    const float* __restrict__ sh_g, const float* __restrict__ sh_b,
    const float* __restrict__ Wg, const float* __restrict__ Wu,
    const float* __restrict__ Wd,
    const float* __restrict__ sWg, const float* __restrict__ sWu,
    const float* __restrict__ sWd)
{
    __shared__ float sx[H_DIM];
    __shared__ float sred[8], sred2[8];
    __shared__ float s_mean, s_rstd;
    __shared__ float logits[N_EXP];

    const int t   = blockIdx.x;
    const int tid = threadIdx.x;
    const float* xr = x + (size_t)t * H_DIM;

    float s = 0.f, s2 = 0.f;
#pragma unroll
    for (int i = 0; i < H_DIM / 256; i++) {
        float v = xr[tid + i * 256];
        sx[tid + i * 256] = v;
        s += v; s2 += v * v;
    }
#pragma unroll
    for (int o = 16; o; o >>= 1) {
        s  += __shfl_xor_sync(0xffffffffu, s,  o);
        s2 += __shfl_xor_sync(0xffffffffu, s2, o);
    }
    const int wid = tid >> 5, lane = tid & 31;
    if (lane == 0) { sred[wid] = s; sred2[wid] = s2; }
    __syncthreads();
    if (tid == 0) {
        float a = 0.f, b = 0.f;
        for (int i = 0; i < 8; i++) { a += sred[i]; b += sred2[i]; }
        float mean = a * (1.f / H_DIM);
        float var  = b * (1.f / H_DIM) - mean * mean;
        s_mean = mean;
        s_rstd = rsqrtf(var + 1e-5f);
    }
    __syncthreads();
    const float mean = s_mean, rstd = s_rstd;

    {
        const float* gw = gate_w + wid * H_DIM;
        float acc = 0.f;
        for (int i = lane; i < H_DIM; i += 32) {
            float hn = (sx[i] - mean) * rstd * ln_g[i] + ln_b[i];
            acc += hn * gw[i];
        }
#pragma unroll
        for (int o = 16; o; o >>= 1) acc += __shfl_xor_sync(0xffffffffu, acc, o);
        if (lane == 0) logits[wid] = acc + bias[wid];
    }

    // x -> half, shared-expert LN -> half (from smem copy, free)
#pragma unroll
    for (int i = 0; i < H_DIM / 256; i++) {
        int idx = tid + i * 256;
        float v = sx[idx];
        g_xh [(size_t)t * H_DIM + idx] = __float2half_rn(v);
        float vn = (v - mean) * rstd * sh_g[idx] + sh_b[idx];
        g_xsh[(size_t)t * H_DIM + idx] = __float2half_rn(vn);
    }
    __syncthreads();

    if (tid == 0) {
        float mx = logits[0];
#pragma unroll
        for (int e = 1; e < N_EXP; e++) mx = fmaxf(mx, logits[e]);
        float p[N_EXP]; float se = 0.f;
#pragma unroll
        for (int e = 0; e < N_EXP; e++) { p[e] = expf(logits[e] - mx); se += p[e]; }
        float z = mx + logf(se);
        g_zsq[t] = z * z;
        int e1 = 0;
#pragma unroll
        for (int e = 1; e < N_EXP; e++) if (p[e] > p[e1]) e1 = e;
        int e2 = (e1 == 0) ? 1 : 0;
#pragma unroll
        for (int e = 0; e < N_EXP; e++) if (e != e1 && p[e] > p[e2]) e2 = e;
        float inv = 1.f / se;
        float p1 = p[e1] * inv, p2 = p[e2] * inv;
        float sm = fmaxf(p1 + p2, 1e-5f);
        int pos = atomicAdd(&g_cnt[e1], 1);
        g_tok[e1][pos] = t; g_wt[e1][pos] = p1 / sm; g_slot[e1][pos] = 2 * t;
        pos = atomicAdd(&g_cnt[e2], 1);
        g_tok[e2][pos] = t; g_wt[e2][pos] = p2 / sm; g_slot[e2][pos] = 2 * t + 1;
    }

    // fused weight conversion (grid-stride over all 6 weight tensors)
    for (unsigned i = blockIdx.x * 256u + tid; i < NWTOT; i += 4096u * 256u) {
        const float* sp; __half* d; unsigned off;
        if (i < GW)                 { sp = Wg;  d = g_hWg;  off = i; }
        else if (i < 2u*GW)         { sp = Wu;  d = g_hWu;  off = i - GW; }
        else if (i < 3u*GW)         { sp = Wd;  d = g_hWd;  off = i - 2u*GW; }
        else if (i < 3u*GW + GS)    { sp = sWg; d = g_hsWg; off = i - 3u*GW; }
        else if (i < 3u*GW + 2u*GS) { sp = sWu; d = g_hsWu; off = i - 3u*GW - GS; }
        else                        { sp = sWd; d = g_hsWd; off = i - 3u*GW - 2u*GS; }
        float4 a = ((const float4*)sp)[2 * (size_t)off];
        float4 b = ((const float4*)sp)[2 * (size_t)off + 1];
        ((uint4*)d)[off] = cvt8(a, b);
    }
}

// ===== HMMA GEMMs: 128x128 block, 8 warps of 32x64, BK=32, 2 CTAs/SM =====
#define BM 128
#define BK 32
#define NSTAGE 5
#define TILE_PITCH 80
#define TILE_BYTES (128 * TILE_PITCH)
#define B_OFF TILE_BYTES
#define STAGE_BYTES (2 * TILE_BYTES)   // 20480
#define SMEM_DYN (NSTAGE * STAGE_BYTES + 1024)

#define MMA16816(d, a, b) \
  asm volatile("mma.sync.aligned.m16n8k16.row.col.f32.f16.f16.f32 " \
    "{%0,%1,%2,%3}, {%4,%5,%6,%7}, {%8,%9}, {%0,%1,%2,%3};" \
    : "+f"((d)[0]), "+f"((d)[1]), "+f"((d)[2]), "+f"((d)[3]) \
    : "r"((a)[0]), "r"((a)[1]), "r"((a)[2]), "r"((a)[3]), "r"((b)[0]), "r"((b)[1]))

#define LDSM4(r0, r1, r2, r3, addr) \
  asm volatile("ldmatrix.sync.aligned.m8n8.x4.shared.b16 {%0,%1,%2,%3}, [%4];" \
    : "=r"(r0), "=r"(r1), "=r"(r2), "=r"(r3) : "r"(addr))

#define CPA16(dst, src, sz) \
  asm volatile("cp.async.cg.shared.global [%0], [%1], 16, %2;" \
    :: "r"(dst), "l"(src), "r"(sz))
#define CPCOMMIT() asm volatile("cp.async.commit_group;")
#define CPWAIT(n)  asm volatile("cp.async.wait_group %0;" :: "n"(n))

// fused gate/up GEMM + SwiGLU.  z: 0..7 routed, 8 = shared.
// B tile rows: [0:32)=Wg n0+0..31, [32:64)=Wu n0+0..31,
//              [64:96)=Wg n0+32..63, [96:128)=Wu n0+32..63.
__global__ void __launch_bounds__(256, 2) hm_gateup(
    const __half* __restrict__ xh,  const __half* __restrict__ xsh,
    const __half* __restrict__ Wg_all, const __half* __restrict__ Wu_all,
    const __half* __restrict__ sWg, const __half* __restrict__ sWu)
{
    extern __shared__ uint8_t dsm[];
    const int e = blockIdx.z;
    const bool se = (e == N_EXP);
    const int cnt = se ? T_TOK : g_cnt[e];
    const int m0 = blockIdx.x * BM;
    if (m0 >= cnt) return;
    const int n0 = blockIdx.y * 64;

    const __half* xp = se ? xsh : xh;
    const __half* wg = se ? sWg : Wg_all + (size_t)e * I_DIM * H_DIM;
    const __half* wu = se ? sWu : Wu_all + (size_t)e * I_DIM * H_DIM;
    __half* hid = se ? g_shid : g_hidden;

    const int tid  = threadIdx.x;
    const int lane = tid & 31;
    const int wid  = tid >> 5;
    const int wm   = (wid & 3) * 32;
    const int wn   = (wid >> 2) * 64;
    const int fr   = lane >> 2;
    const int fc   = lane & 3;

    // loaders: row tid&127, two 16B segs at (tid>>7)*2
    const int arow = tid & 127;
    const int ah   = (tid >> 7) * 2;
    const __half* aptr = xp;
    uint32_t asz = 0;
    if (m0 + arow < cnt) {
        int r = se ? (m0 + arow) : g_tok[e][m0 + arow];
        aptr = xp + (size_t)r * H_DIM;
        asz = 16u;
    }
    const int brow = tid & 127;
    const __half* bbase = (brow & 32) ? wu : wg;
    const __half* bptr = bbase + (size_t)(n0 + ((brow >> 6) << 5) + (brow & 31)) * H_DIM;

    const uint32_t sb = (smem_u32(dsm) + 1023) & ~1023u;
    const uint32_t adst = sb + arow * TILE_PITCH + ah * 16;
    const uint32_t bdst = sb + B_OFF + brow * TILE_PITCH + ah * 16;
    const uint32_t loff = (uint32_t)(((lane & 7) + ((lane >> 3) & 1) * 8) * TILE_PITCH
                                     + ((lane >> 4) & 1) * 16);
    const uint32_t aw = loff + wm * TILE_PITCH;
    const uint32_t bw = loff + B_OFF + wn * TILE_PITCH;

    float acc[2][8][4] = {};
    const int NCH = H_DIM / BK;   // 32

#define GU_ISSUE(c, sl) do { \
    uint32_t st_ = (uint32_t)(sl) * STAGE_BYTES; \
    const __half* a_ = aptr + (c) * BK + ah * 8; \
    const __half* b_ = bptr + (c) * BK + ah * 8; \
    CPA16(adst + st_,      a_,     asz); \
    CPA16(adst + st_ + 16, a_ + 8, asz); \
    CPA16(bdst + st_,      b_,     16u); \
    CPA16(bdst + st_ + 16, b_ + 8, 16u); \
} while (0)

#pragma unroll
    for (int s = 0; s < NSTAGE - 1; s++) { GU_ISSUE(s, s); CPCOMMIT(); }

    int sl = 0;                 // slot of chunk c
    for (int c = 0; c < NCH; c++) {
        CPWAIT(NSTAGE - 2);
        __syncthreads();
        int cc = c + NSTAGE - 1;
        if (cc < NCH) {
            int sl2 = sl + NSTAGE - 1; if (sl2 >= NSTAGE) sl2 -= NSTAGE;
            GU_ISSUE(cc, sl2);
        }
        CPCOMMIT();
        const uint32_t stb = sb + (uint32_t)sl * STAGE_BYTES;
        const uint32_t Aw = stb + aw;
        const uint32_t Bw = stb + bw;
#pragma unroll
        for (int s = 0; s < 2; s++) {
            uint32_t a[2][4];
            uint32_t b[8][2];
            LDSM4(a[0][0], a[0][1], a[0][2], a[0][3], Aw + s * 32);
            LDSM4(a[1][0], a[1][1], a[1][2], a[1][3], Aw + 16 * TILE_PITCH + s * 32);
            {
                uint32_t q0, q1, q2, q3;
                LDSM4(q0, q1, q2, q3, Bw + s * 32);
                b[0][0] = q0; b[0][1] = q2; b[1][0] = q1; b[1][1] = q3;
                LDSM4(q0, q1, q2, q3, Bw + 16 * TILE_PITCH + s * 32);
                b[2][0] = q0; b[2][1] = q2; b[3][0] = q1; b[3][1] = q3;
            }
#pragma unroll
            for (int mt = 0; mt < 2; mt++)
#pragma unroll
                for (int nt = 0; nt < 4; nt++)
                    MMA16816(acc[mt][nt], a[mt], b[nt]);
            {
                uint32_t q0, q1, q2, q3;
                LDSM4(q0, q1, q2, q3, Bw + 32 * TILE_PITCH + s * 32);
                b[4][0] = q0; b[4][1] = q2; b[5][0] = q1; b[5][1] = q3;
                LDSM4(q0, q1, q2, q3, Bw + 48 * TILE_PITCH + s * 32);
                b[6][0] = q0; b[6][1] = q2; b[7][0] = q1; b[7][1] = q3;
            }
#pragma unroll
            for (int mt = 0; mt < 2; mt++)
#pragma unroll
                for (int nt = 4; nt < 8; nt++)
                    MMA16816(acc[mt][nt], a[mt], b[nt]);
        }
        if (++sl == NSTAGE) sl = 0;
    }

    // epilogue: silu(gate)*up; nt 0..3 gate, 4..7 matching up
    const int colbase = n0 + (wn >> 1);
#pragma unroll
    for (int mt = 0; mt < 2; mt++) {
#pragma unroll
        for (int i2 = 0; i2 < 2; i2++) {
            int row = wm + mt * 16 + fr + i2 * 8;
            int m = m0 + row;
            if (m >= cnt) continue;
            int orow = se ? m : g_slot[e][m];
            __half* op = hid + (size_t)orow * I_DIM + colbase;
#pragma unroll
            for (int j = 0; j < 4; j++) {
                float g0 = acc[mt][j][i2*2+0],   g1 = acc[mt][j][i2*2+1];
                float u0 = acc[mt][4+j][i2*2+0], u1 = acc[mt][4+j][i2*2+1];
                float v0 = (g0 / (1.f + expf(-g0))) * u0;
                float v1 = (g1 / (1.f + expf(-g1))) * u1;
                *(half2*)(op + j * 8 + 2 * fc) = __floats2half2_rn(v0, v1);
            }
        }
    }
}

// down GEMM (+ combine weight for routed). 128 H-cols per block.
__global__ void __launch_bounds__(256, 2) hm_down(
    const __half* __restrict__ Wd_all, const __half* __restrict__ sWd)
{
    extern __shared__ uint8_t dsm[];
    const int e = blockIdx.z;
    const bool se = (e == N_EXP);
    const int cnt = se ? T_TOK : g_cnt[e];
    const int m0 = blockIdx.x * BM;
    if (m0 >= cnt) return;
    const int n0 = blockIdx.y * 128;

    const __half* hid = se ? g_shid : g_hidden;
    const __half* wd  = se ? sWd : Wd_all + (size_t)e * H_DIM * I_DIM;

    const int tid  = threadIdx.x;
    const int lane = tid & 31;
    const int wid  = tid >> 5;
    const int wm   = (wid & 3) * 32;
    const int wn   = (wid >> 2) * 64;
    const int fr   = lane >> 2;
    const int fc   = lane & 3;

    const int arow = tid & 127;
    const int ah   = (tid >> 7) * 2;
    const __half* aptr = hid;
    uint32_t asz = 0;
    if (m0 + arow < cnt) {
        int slot = se ? (m0 + arow) : g_slot[e][m0 + arow];
        aptr = hid + (size_t)slot * I_DIM;
        asz = 16u;
    }
    const int brow = tid & 127;
    const __half* bptr = wd + (size_t)(n0 + brow) * I_DIM;

    const uint32_t sb = (smem_u32(dsm) + 1023) & ~1023u;
    const uint32_t adst = sb + arow * TILE_PITCH + ah * 16;
    const uint32_t bdst = sb + B_OFF + brow * TILE_PITCH + ah * 16;
    const uint32_t loff = (uint32_t)(((lane & 7) + ((lane >> 3) & 1) * 8) * TILE_PITCH
                                     + ((lane >> 4) & 1) * 16);
    const uint32_t aw = loff + wm * TILE_PITCH;
    const uint32_t bw = loff + B_OFF + wn * TILE_PITCH;

    float acc[2][8][4] = {};
    const int NCH = I_DIM / BK;   // 64

#define DN_ISSUE(c, sl) do { \
    uint32_t st_ = (uint32_t)(sl) * STAGE_BYTES; \
    const __half* a_ = aptr + (c) * BK + ah * 8; \
    const __half* b_ = bptr + (c) * BK + ah * 8; \
    CPA16(adst + st_,      a_,     asz); \
    CPA16(adst + st_ + 16, a_ + 8, asz); \
    CPA16(bdst + st_,      b_,     16u); \
    CPA16(bdst + st_ + 16, b_ + 8, 16u); \
} while (0)

#pragma unroll
    for (int s = 0; s < NSTAGE - 1; s++) { DN_ISSUE(s, s); CPCOMMIT(); }

    int sl = 0;
    for (int c = 0; c < NCH; c++) {
        CPWAIT(NSTAGE - 2);
        __syncthreads();
        int cc = c + NSTAGE - 1;
        if (cc < NCH) {
            int sl2 = sl + NSTAGE - 1; if (sl2 >= NSTAGE) sl2 -= NSTAGE;
            DN_ISSUE(cc, sl2);
        }
        CPCOMMIT();
        const uint32_t stb = sb + (uint32_t)sl * STAGE_BYTES;
        const uint32_t Aw = stb + aw;
        const uint32_t Bw = stb + bw;
#pragma unroll
        for (int s = 0; s < 2; s++) {
            uint32_t a[2][4];
            uint32_t b[8][2];
            LDSM4(a[0][0], a[0][1], a[0][2], a[0][3], Aw + s * 32);
            LDSM4(a[1][0], a[1][1], a[1][2], a[1][3], Aw + 16 * TILE_PITCH + s * 32);
            {
                uint32_t q0, q1, q2, q3;
                LDSM4(q0, q1, q2, q3, Bw + s * 32);
                b[0][0] = q0; b[0][1] = q2; b[1][0] = q1; b[1][1] = q3;
                LDSM4(q0, q1, q2, q3, Bw + 16 * TILE_PITCH + s * 32);
                b[2][0] = q0; b[2][1] = q2; b[3][0] = q1; b[3][1] = q3;
            }
#pragma unroll
            for (int mt = 0; mt < 2; mt++)
#pragma unroll
                for (int nt = 0; nt < 4; nt++)
                    MMA16816(acc[mt][nt], a[mt], b[nt]);
            {
                uint32_t q0, q1, q2, q3;
                LDSM4(q0, q1, q2, q3, Bw + 32 * TILE_PITCH + s * 32);
                b[4][0] = q0; b[4][1] = q2; b[5][0] = q1; b[5][1] = q3;
                LDSM4(q0, q1, q2, q3, Bw + 48 * TILE_PITCH + s * 32);
                b[6][0] = q0; b[6][1] = q2; b[7][0] = q1; b[7][1] = q3;
            }
#pragma unroll
            for (int mt = 0; mt < 2; mt++)
#pragma unroll
                for (int nt = 4; nt < 8; nt++)
                    MMA16816(acc[mt][nt], a[mt], b[nt]);
        }
        if (++sl == NSTAGE) sl = 0;
    }

#pragma unroll
    for (int mt = 0; mt < 2; mt++) {
#pragma unroll
        for (int i2 = 0; i2 < 2; i2++) {
            int row = wm + mt * 16 + fr + i2 * 8;
            int m = m0 + row;
            if (m >= cnt) continue;
            if (se) {
                float* op = g_shout + (size_t)m * H_DIM + n0 + wn;
#pragma unroll
                for (int nt = 0; nt < 8; nt++) {
                    float2 v;
                    v.x = acc[mt][nt][i2*2+0];
                    v.y = acc[mt][nt][i2*2+1];
                    *(float2*)(op + nt * 8 + 2 * fc) = v;
                }
            } else {
                int orow = g_slot[e][m];
                float w  = g_wt[e][m];
                float* op = g_eout + (size_t)orow * H_DIM + n0 + wn;
#pragma unroll
                for (int nt = 0; nt < 8; nt++) {
                    float2 v;
                    v.x = acc[mt][nt][i2*2+0] * w;
                    v.y = acc[mt][nt][i2*2+1] * w;
                    *(float2*)(op + nt * 8 + 2 * fc) = v;
                }
            }
        }
    }
}

// ---------------- combine ----------------
__global__ void __launch_bounds__(256) combine_kernel(
    float* __restrict__ out, const float* __restrict__ shared_gate)
{
    const int idx = blockIdx.x * 256 + threadIdx.x;
    const float sig = 1.f / (1.f + expf(-shared_gate[0]));
    const int t = idx >> 10;
    const int h = idx & (H_DIM - 1);
    out[idx] = g_eout[(size_t)(2 * t) * H_DIM + h]
             + g_eout[(size_t)(2 * t + 1) * H_DIM + h]
             + g_shout[idx] * sig;
}

// ---------------- aux z-loss ----------------
__global__ void __launch_bounds__(256) aux_kernel(float* __restrict__ out)
{
    __shared__ float red[256];
    const int tid = threadIdx.x;
    float s = 0.f;
    for (int i = tid; i < T_TOK; i += 256) s += g_zsq[i];
    red[tid] = s;
    __syncthreads();
    for (int o = 128; o; o >>= 1) {
        if (tid < o) red[tid] += red[tid + o];
        __syncthreads();
    }
    if (tid == 0) out[(size_t)T_TOK * H_DIM] = red[0] * (1e-4f / T_TOK);
}

// ---------------- launch ----------------
extern "C" void kernel_launch(void* const* d_in, const int* in_sizes, int n_in,
                              void* d_out, int out_size)
{
    const float* x      = (const float*)d_in[0];
    const float* ln_g   = (const float*)d_in[1];
    const float* ln_b   = (const float*)d_in[2];
    const float* gate_w = (const float*)d_in[3];
    const float* bias   = (const float*)d_in[4];
    const float* Wg     = (const float*)d_in[5];
    const float* Wu     = (const float*)d_in[6];
    const float* Wd     = (const float*)d_in[7];
    const float* sh_g   = (const float*)d_in[8];
    const float* sh_b   = (const float*)d_in[9];
    const float* sWg    = (const float*)d_in[10];
    const float* sWu    = (const float*)d_in[11];
    const float* sWd    = (const float*)d_in[12];
    const float* sgate  = (const float*)d_in[13];
    float* out = (float*)d_out;

    static int attr_done = 0;
    if (!attr_done) {
        cudaFuncSetAttribute(hm_gateup,
            cudaFuncAttributeMaxDynamicSharedMemorySize, SMEM_DYN);
        cudaFuncSetAttribute(hm_down,
            cudaFuncAttributeMaxDynamicSharedMemorySize, SMEM_DYN);
        attr_done = 1;
    }

    __half *xh, *xsh;
    cudaGetSymbolAddress((void**)&xh,  g_xh);
    cudaGetSymbolAddress((void**)&xsh, g_xsh);
    __half *hWg, *hWu, *hWd, *hsWg, *hsWu, *hsWd;
    cudaGetSymbolAddress((void**)&hWg, g_hWg);
    cudaGetSymbolAddress((void**)&hWu, g_hWu);
    cudaGetSymbolAddress((void**)&hWd, g_hWd);
    cudaGetSymbolAddress((void**)&hsWg, g_hsWg);
    cudaGetSymbolAddress((void**)&hsWu, g_hsWu);
    cudaGetSymbolAddress((void**)&hsWd, g_hsWd);

    zero_cnt_kernel<<<1, 32>>>();                                           // 1
    router_kernel<<<T_TOK, 256>>>(x, ln_g, ln_b, gate_w, bias, sh_g, sh_b,
                                  Wg, Wu, Wd, sWg, sWu, sWd);               // 2

    dim3 gu_grid(T_TOK / BM, I_DIM / 64, N_EXP + 1);
    hm_gateup<<<gu_grid, 256, SMEM_DYN>>>(xh, xsh, hWg, hWu, hsWg, hsWu);   // 3

    dim3 dn_grid(T_TOK / BM, H_DIM / 128, N_EXP + 1);
    hm_down<<<dn_grid, 256, SMEM_DYN>>>(hWd, hsWd);                         // 4 (profiled)

    combine_kernel<<<(T_TOK * H_DIM) / 256, 256>>>(out, sgate);             // 5
    aux_kernel<<<1, 256>>>(out);                                            // 6
}

// round 15
// speedup vs baseline: 1.1690x; 1.0973x over previous
#include <cuda_runtime.h>
#include <cuda_fp16.h>
#include <stdint.h>
#include <math.h>

// Problem constants
#define T_TOK 4096
#define H_DIM 1024
#define I_DIM 2048
#define N_EXP 8

// ---------------- scratch (static device globals; no allocs) ----------------
__device__ int    g_cnt[N_EXP];
__device__ int    g_tok[N_EXP][T_TOK];
__device__ float  g_wt [N_EXP][T_TOK];
__device__ int    g_slot[N_EXP][T_TOK];
__device__ __half g_hidden[(size_t)2 * T_TOK * I_DIM];
__device__ float  g_eout [(size_t)2 * T_TOK * H_DIM];
__device__ __half g_shid [(size_t)T_TOK * I_DIM];
__device__ float  g_shout[(size_t)T_TOK * H_DIM];
__device__ float  g_zsq[T_TOK];

__device__ __half g_xh  [(size_t)T_TOK * H_DIM];
__device__ __half g_xsh [(size_t)T_TOK * H_DIM];
__device__ __half g_hWg [(size_t)N_EXP * I_DIM * H_DIM];
__device__ __half g_hWu [(size_t)N_EXP * I_DIM * H_DIM];
__device__ __half g_hWd [(size_t)N_EXP * H_DIM * I_DIM];
__device__ __half g_hsWg[(size_t)I_DIM * H_DIM];
__device__ __half g_hsWu[(size_t)I_DIM * H_DIM];
__device__ __half g_hsWd[(size_t)H_DIM * I_DIM];

__device__ __forceinline__ uint32_t h2u(half2 h) { return *(uint32_t*)&h; }
__device__ __forceinline__ uint32_t smem_u32(const void* p) {
    return (uint32_t)__cvta_generic_to_shared(p);
}
__device__ __forceinline__ uint4 cvt8(float4 a, float4 b) {
    uint4 r;
    r.x = h2u(__floats2half2_rn(a.x, a.y));
    r.y = h2u(__floats2half2_rn(a.z, a.w));
    r.z = h2u(__floats2half2_rn(b.x, b.y));
    r.w = h2u(__floats2half2_rn(b.z, b.w));
    return r;
}

#define GW  (N_EXP * I_DIM * H_DIM / 8)
#define GS  (I_DIM * H_DIM / 8)
#define NWTOT (3u * GW + 3u * GS)

__global__ void zero_cnt_kernel() {
    if (threadIdx.x < N_EXP) g_cnt[threadIdx.x] = 0;
}

// ---------------- router (+ fused fp32->fp16 conversion) ----------------
__global__ void __launch_bounds__(256) router_kernel(
    const float* __restrict__ x,
    const float* __restrict__ ln_g, const float* __restrict__ ln_b,
    const float* __restrict__ gate_w, const float* __restrict__ bias,
    const float* __restrict__ sh_g, const float* __restrict__ sh_b,
    const float* __restrict__ Wg, const float* __restrict__ Wu,
    const float* __restrict__ Wd,
    const float* __restrict__ sWg, const float* __restrict__ sWu,
    const float* __restrict__ sWd)
{
    __shared__ float sx[H_DIM];
    __shared__ float sred[8], sred2[8];
    __shared__ float s_mean, s_rstd;
    __shared__ float logits[N_EXP];

    const int t   = blockIdx.x;
    const int tid = threadIdx.x;
    const float* xr = x + (size_t)t * H_DIM;

    float s = 0.f, s2 = 0.f;
#pragma unroll
    for (int i = 0; i < H_DIM / 256; i++) {
        float v = xr[tid + i * 256];
        sx[tid + i * 256] = v;
        s += v; s2 += v * v;
    }
#pragma unroll
    for (int o = 16; o; o >>= 1) {
        s  += __shfl_xor_sync(0xffffffffu, s,  o);
        s2 += __shfl_xor_sync(0xffffffffu, s2, o);
    }
    const int wid = tid >> 5, lane = tid & 31;
    if (lane == 0) { sred[wid] = s; sred2[wid] = s2; }
    __syncthreads();
    if (tid == 0) {
        float a = 0.f, b = 0.f;
        for (int i = 0; i < 8; i++) { a += sred[i]; b += sred2[i]; }
        float mean = a * (1.f / H_DIM);
        float var  = b * (1.f / H_DIM) - mean * mean;
        s_mean = mean;
        s_rstd = rsqrtf(var + 1e-5f);
    }
    __syncthreads();
    const float mean = s_mean, rstd = s_rstd;

    {
        const float* gw = gate_w + wid * H_DIM;
        float acc = 0.f;
        for (int i = lane; i < H_DIM; i += 32) {
            float hn = (sx[i] - mean) * rstd * ln_g[i] + ln_b[i];
            acc += hn * gw[i];
        }
#pragma unroll
        for (int o = 16; o; o >>= 1) acc += __shfl_xor_sync(0xffffffffu, acc, o);
        if (lane == 0) logits[wid] = acc + bias[wid];
    }

#pragma unroll
    for (int i = 0; i < H_DIM / 256; i++) {
        int idx = tid + i * 256;
        float v = sx[idx];
        g_xh [(size_t)t * H_DIM + idx] = __float2half_rn(v);
        float vn = (v - mean) * rstd * sh_g[idx] + sh_b[idx];
        g_xsh[(size_t)t * H_DIM + idx] = __float2half_rn(vn);
    }
    __syncthreads();

    if (tid == 0) {
        float mx = logits[0];
#pragma unroll
        for (int e = 1; e < N_EXP; e++) mx = fmaxf(mx, logits[e]);
        float p[N_EXP]; float se = 0.f;
#pragma unroll
        for (int e = 0; e < N_EXP; e++) { p[e] = expf(logits[e] - mx); se += p[e]; }
        float z = mx + logf(se);
        g_zsq[t] = z * z;
        int e1 = 0;
#pragma unroll
        for (int e = 1; e < N_EXP; e++) if (p[e] > p[e1]) e1 = e;
        int e2 = (e1 == 0) ? 1 : 0;
#pragma unroll
        for (int e = 0; e < N_EXP; e++) if (e != e1 && p[e] > p[e2]) e2 = e;
        float inv = 1.f / se;
        float p1 = p[e1] * inv, p2 = p[e2] * inv;
        float sm = fmaxf(p1 + p2, 1e-5f);
        int pos = atomicAdd(&g_cnt[e1], 1);
        g_tok[e1][pos] = t; g_wt[e1][pos] = p1 / sm; g_slot[e1][pos] = 2 * t;
        pos = atomicAdd(&g_cnt[e2], 1);
        g_tok[e2][pos] = t; g_wt[e2][pos] = p2 / sm; g_slot[e2][pos] = 2 * t + 1;
    }

    for (unsigned i = blockIdx.x * 256u + tid; i < NWTOT; i += 4096u * 256u) {
        const float* sp; __half* d; unsigned off;
        if (i < GW)                 { sp = Wg;  d = g_hWg;  off = i; }
        else if (i < 2u*GW)         { sp = Wu;  d = g_hWu;  off = i - GW; }
        else if (i < 3u*GW)         { sp = Wd;  d = g_hWd;  off = i - 2u*GW; }
        else if (i < 3u*GW + GS)    { sp = sWg; d = g_hsWg; off = i - 3u*GW; }
        else if (i < 3u*GW + 2u*GS) { sp = sWu; d = g_hsWu; off = i - 3u*GW - GS; }
        else                        { sp = sWd; d = g_hsWd; off = i - 3u*GW - 2u*GS; }
        float4 a = ((const float4*)sp)[2 * (size_t)off];
        float4 b = ((const float4*)sp)[2 * (size_t)off + 1];
        ((uint4*)d)[off] = cvt8(a, b);
    }
}

// ===== HMMA GEMMs: 128x128 block, 4 warps of 64x64, 128 thr, frag-pipelined =====
#define BM 128
#define BK 32
#define NSTAGE 5
#define TILE_PITCH 80
#define TILE_BYTES (128 * TILE_PITCH)
#define B_OFF TILE_BYTES
#define STAGE_BYTES (2 * TILE_BYTES)   // 20480
#define SMEM_DYN (NSTAGE * STAGE_BYTES + 1024)

#define MMA16816(d, a, b) \
  asm volatile("mma.sync.aligned.m16n8k16.row.col.f32.f16.f16.f32 " \
    "{%0,%1,%2,%3}, {%4,%5,%6,%7}, {%8,%9}, {%0,%1,%2,%3};" \
    : "+f"((d)[0]), "+f"((d)[1]), "+f"((d)[2]), "+f"((d)[3]) \
    : "r"((a)[0]), "r"((a)[1]), "r"((a)[2]), "r"((a)[3]), "r"((b)[0]), "r"((b)[1]))

#define LDSM4(r0, r1, r2, r3, addr) \
  asm volatile("ldmatrix.sync.aligned.m8n8.x4.shared.b16 {%0,%1,%2,%3}, [%4];" \
    : "=r"(r0), "=r"(r1), "=r"(r2), "=r"(r3) : "r"(addr))

#define CPA16(dst, src, sz) \
  asm volatile("cp.async.cg.shared.global [%0], [%1], 16, %2;" \
    :: "r"(dst), "l"(src), "r"(sz))
#define CPCOMMIT() asm volatile("cp.async.commit_group;")
#define CPWAIT(n)  asm volatile("cp.async.wait_group %0;" :: "n"(n))

// load fragment set for one k16 slice from stage base stb_ into fa/fb
#define LOADFRAG(fa, fb, stb_, soff) do { \
    const uint32_t Aw_ = (stb_) + loff + wm * TILE_PITCH + (soff); \
    const uint32_t Bw_ = (stb_) + B_OFF + loff + wn * TILE_PITCH + (soff); \
    _Pragma("unroll") \
    for (int mt = 0; mt < 4; mt++) \
        LDSM4((fa)[mt][0], (fa)[mt][1], (fa)[mt][2], (fa)[mt][3], \
              Aw_ + mt * (16 * TILE_PITCH)); \
    _Pragma("unroll") \
    for (int np = 0; np < 4; np++) { \
        uint32_t q0, q1, q2, q3; \
        LDSM4(q0, q1, q2, q3, Bw_ + np * (16 * TILE_PITCH)); \
        (fb)[2*np][0] = q0; (fb)[2*np][1] = q2; \
        (fb)[2*np+1][0] = q1; (fb)[2*np+1][1] = q3; \
    } \
} while (0)

#define MMASET(fa, fb) do { \
    _Pragma("unroll") \
    for (int mt = 0; mt < 4; mt++) \
        _Pragma("unroll") \
        for (int nt = 0; nt < 8; nt++) \
            MMA16816(acc[mt][nt], (fa)[mt], (fb)[nt]); \
} while (0)

// fused gate/up GEMM + SwiGLU.  z: 0..7 routed, 8 = shared.
// B tile rows: [0:32)=Wg n0+0..31, [32:64)=Wu n0+0..31,
//              [64:96)=Wg n0+32..63, [96:128)=Wu n0+32..63.
__global__ void __launch_bounds__(128, 2) hm_gateup(
    const __half* __restrict__ xh,  const __half* __restrict__ xsh,
    const __half* __restrict__ Wg_all, const __half* __restrict__ Wu_all,
    const __half* __restrict__ sWg, const __half* __restrict__ sWu)
{
    extern __shared__ uint8_t dsm[];
    const int e = blockIdx.z;
    const bool se = (e == N_EXP);
    const int cnt = se ? T_TOK : g_cnt[e];
    const int m0 = blockIdx.x * BM;
    if (m0 >= cnt) return;
    const int n0 = blockIdx.y * 64;

    const __half* xp = se ? xsh : xh;
    const __half* wg = se ? sWg : Wg_all + (size_t)e * I_DIM * H_DIM;
    const __half* wu = se ? sWu : Wu_all + (size_t)e * I_DIM * H_DIM;
    __half* hid = se ? g_shid : g_hidden;

    const int tid  = threadIdx.x;     // 0..127
    const int lane = tid & 31;
    const int wid  = tid >> 5;        // 0..3
    const int wm   = (wid & 1) * 64;
    const int wn   = (wid >> 1) * 64;
    const int fr   = lane >> 2;
    const int fc   = lane & 3;

    // loaders: thread tid -> A row tid (4 segs), B row tid (4 segs)
    const __half* aptr = xp;
    uint32_t asz = 0;
    if (m0 + tid < cnt) {
        int r = se ? (m0 + tid) : g_tok[e][m0 + tid];
        aptr = xp + (size_t)r * H_DIM;
        asz = 16u;
    }
    const __half* bbase = (tid & 32) ? wu : wg;
    const __half* bptr = bbase + (size_t)(n0 + ((tid >> 6) << 5) + (tid & 31)) * H_DIM;

    const uint32_t sb = (smem_u32(dsm) + 1023) & ~1023u;
    const uint32_t adst = sb + tid * TILE_PITCH;
    const uint32_t bdst = sb + B_OFF + tid * TILE_PITCH;
    const uint32_t loff = (uint32_t)(((lane & 7) + ((lane >> 3) & 1) * 8) * TILE_PITCH
                                     + ((lane >> 4) & 1) * 16);

    float acc[4][8][4] = {};
    uint32_t fa0[4][4], fb0[8][2], fa1[4][4], fb1[8][2];
    const int NCH = H_DIM / BK;   // 32

#define GU_ISSUE(c, SLOT) do { \
    uint32_t st_ = sb + (uint32_t)(SLOT) * STAGE_BYTES; \
    const __half* a_ = aptr + (c) * BK; \
    const __half* b_ = bptr + (c) * BK; \
    _Pragma("unroll") \
    for (int q = 0; q < 4; q++) { \
        CPA16(adst + ((uint32_t)(SLOT)) * STAGE_BYTES + q * 16, a_ + q * 8, asz); \
        CPA16(bdst + ((uint32_t)(SLOT)) * STAGE_BYTES + q * 16, b_ + q * 8, 16u); \
    } \
    (void)st_; \
} while (0)

    GU_ISSUE(0, 0); CPCOMMIT();
    GU_ISSUE(1, 1); CPCOMMIT();
    GU_ISSUE(2, 2); CPCOMMIT();
    GU_ISSUE(3, 3); CPCOMMIT();

    CPWAIT(2);
    __syncthreads();
    LOADFRAG(fa0, fb0, sb, 0);        // chunk 0, slice 0 (slot 0)

    int sl = 0;
    for (int c = 0; c < NCH; c++) {
        CPWAIT(2);
        __syncthreads();
        int cc = c + 4;
        if (cc < NCH) {
            int sl2 = sl + 4; if (sl2 >= NSTAGE) sl2 -= NSTAGE;
            GU_ISSUE(cc, sl2);
        }
        CPCOMMIT();
        const uint32_t stb = sb + (uint32_t)sl * STAGE_BYTES;
        int sln = sl + 1; if (sln == NSTAGE) sln = 0;
        const uint32_t stn = sb + (uint32_t)sln * STAGE_BYTES;
        LOADFRAG(fa1, fb1, stb, 32);  // this chunk, slice 1
        MMASET(fa0, fb0);
        LOADFRAG(fa0, fb0, stn, 0);   // next chunk, slice 0 (stale-safe on last iter)
        MMASET(fa1, fb1);
        sl = sln;
    }

    // epilogue: silu(gate)*up; nt 0..3 gate, 4..7 matching up
    const int colbase = n0 + (wn >> 1);
#pragma unroll
    for (int mt = 0; mt < 4; mt++) {
#pragma unroll
        for (int i2 = 0; i2 < 2; i2++) {
            int row = wm + mt * 16 + fr + i2 * 8;
            int m = m0 + row;
            if (m >= cnt) continue;
            int orow = se ? m : g_slot[e][m];
            __half* op = hid + (size_t)orow * I_DIM + colbase;
#pragma unroll
            for (int j = 0; j < 4; j++) {
                float g0 = acc[mt][j][i2*2+0],   g1 = acc[mt][j][i2*2+1];
                float u0 = acc[mt][4+j][i2*2+0], u1 = acc[mt][4+j][i2*2+1];
                float v0 = (g0 / (1.f + expf(-g0))) * u0;
                float v1 = (g1 / (1.f + expf(-g1))) * u1;
                *(half2*)(op + j * 8 + 2 * fc) = __floats2half2_rn(v0, v1);
            }
        }
    }
}

// down GEMM (+ combine weight for routed). 128 H-cols per block.
__global__ void __launch_bounds__(128, 2) hm_down(
    const __half* __restrict__ Wd_all, const __half* __restrict__ sWd)
{
    extern __shared__ uint8_t dsm[];
    const int e = blockIdx.z;
    const bool se = (e == N_EXP);
    const int cnt = se ? T_TOK : g_cnt[e];
    const int m0 = blockIdx.x * BM;
    if (m0 >= cnt) return;
    const int n0 = blockIdx.y * 128;

    const __half* hid = se ? g_shid : g_hidden;
    const __half* wd  = se ? sWd : Wd_all + (size_t)e * H_DIM * I_DIM;

    const int tid  = threadIdx.x;
    const int lane = tid & 31;
    const int wid  = tid >> 5;
    const int wm   = (wid & 1) * 64;
    const int wn   = (wid >> 1) * 64;
    const int fr   = lane >> 2;
    const int fc   = lane & 3;

    const __half* aptr = hid;
    uint32_t asz = 0;
    if (m0 + tid < cnt) {
        int slot = se ? (m0 + tid) : g_slot[e][m0 + tid];
        aptr = hid + (size_t)slot * I_DIM;
        asz = 16u;
    }
    const __half* bptr = wd + (size_t)(n0 + tid) * I_DIM;

    const uint32_t sb = (smem_u32(dsm) + 1023) & ~1023u;
    const uint32_t adst = sb + tid * TILE_PITCH;
    const uint32_t bdst = sb + B_OFF + tid * TILE_PITCH;
    const uint32_t loff = (uint32_t)(((lane & 7) + ((lane >> 3) & 1) * 8) * TILE_PITCH
                                     + ((lane >> 4) & 1) * 16);

    float acc[4][8][4] = {};
    uint32_t fa0[4][4], fb0[8][2], fa1[4][4], fb1[8][2];
    const int NCH = I_DIM / BK;   // 64

#define DN_ISSUE(c, SLOT) do { \
    const __half* a_ = aptr + (c) * BK; \
    const __half* b_ = bptr + (c) * BK; \
    _Pragma("unroll") \
    for (int q = 0; q < 4; q++) { \
        CPA16(adst + ((uint32_t)(SLOT)) * STAGE_BYTES + q * 16, a_ + q * 8, asz); \
        CPA16(bdst + ((uint32_t)(SLOT)) * STAGE_BYTES + q * 16, b_ + q * 8, 16u); \
    } \
} while (0)

    DN_ISSUE(0, 0); CPCOMMIT();
    DN_ISSUE(1, 1); CPCOMMIT();
    DN_ISSUE(2, 2); CPCOMMIT();
    DN_ISSUE(3, 3); CPCOMMIT();

    CPWAIT(2);
    __syncthreads();
    LOADFRAG(fa0, fb0, sb, 0);

    int sl = 0;
    for (int c = 0; c < NCH; c++) {
        CPWAIT(2);
        __syncthreads();
        int cc = c + 4;
        if (cc < NCH) {
            int sl2 = sl + 4; if (sl2 >= NSTAGE) sl2 -= NSTAGE;
            DN_ISSUE(cc, sl2);
        }
        CPCOMMIT();
        const uint32_t stb = sb + (uint32_t)sl * STAGE_BYTES;
        int sln = sl + 1; if (sln == NSTAGE) sln = 0;
        const uint32_t stn = sb + (uint32_t)sln * STAGE_BYTES;
        LOADFRAG(fa1, fb1, stb, 32);
        MMASET(fa0, fb0);
        LOADFRAG(fa0, fb0, stn, 0);
        MMASET(fa1, fb1);
        sl = sln;
    }

#pragma unroll
    for (int mt = 0; mt < 4; mt++) {
#pragma unroll
        for (int i2 = 0; i2 < 2; i2++) {
            int row = wm + mt * 16 + fr + i2 * 8;
            int m = m0 + row;
            if (m >= cnt) continue;
            if (se) {
                float* op = g_shout + (size_t)m * H_DIM + n0 + wn;
#pragma unroll
                for (int nt = 0; nt < 8; nt++) {
                    float2 v;
                    v.x = acc[mt][nt][i2*2+0];
                    v.y = acc[mt][nt][i2*2+1];
                    *(float2*)(op + nt * 8 + 2 * fc) = v;
                }
            } else {
                int orow = g_slot[e][m];
                float w  = g_wt[e][m];
                float* op = g_eout + (size_t)orow * H_DIM + n0 + wn;
#pragma unroll
                for (int nt = 0; nt < 8; nt++) {
                    float2 v;
                    v.x = acc[mt][nt][i2*2+0] * w;
                    v.y = acc[mt][nt][i2*2+1] * w;
                    *(float2*)(op + nt * 8 + 2 * fc) = v;
                }
            }
        }
    }
}

// ---------------- combine ----------------
__global__ void __launch_bounds__(256) combine_kernel(
    float* __restrict__ out, const float* __restrict__ shared_gate)
{
    const int idx = blockIdx.x * 256 + threadIdx.x;
    const float sig = 1.f / (1.f + expf(-shared_gate[0]));
    const int t = idx >> 10;
    const int h = idx & (H_DIM - 1);
    out[idx] = g_eout[(size_t)(2 * t) * H_DIM + h]
             + g_eout[(size_t)(2 * t + 1) * H_DIM + h]
             + g_shout[idx] * sig;
}

// ---------------- aux z-loss ----------------
__global__ void __launch_bounds__(256) aux_kernel(float* __restrict__ out)
{
    __shared__ float red[256];
    const int tid = threadIdx.x;
    float s = 0.f;
    for (int i = tid; i < T_TOK; i += 256) s += g_zsq[i];
    red[tid] = s;
    __syncthreads();
    for (int o = 128; o; o >>= 1) {
        if (tid < o) red[tid] += red[tid + o];
        __syncthreads();
    }
    if (tid == 0) out[(size_t)T_TOK * H_DIM] = red[0] * (1e-4f / T_TOK);
}

// ---------------- launch ----------------
extern "C" void kernel_launch(void* const* d_in, const int* in_sizes, int n_in,
                              void* d_out, int out_size)
{
    const float* x      = (const float*)d_in[0];
    const float* ln_g   = (const float*)d_in[1];
    const float* ln_b   = (const float*)d_in[2];
    const float* gate_w = (const float*)d_in[3];
    const float* bias   = (const float*)d_in[4];
    const float* Wg     = (const float*)d_in[5];
    const float* Wu     = (const float*)d_in[6];
    const float* Wd     = (const float*)d_in[7];
    const float* sh_g   = (const float*)d_in[8];
    const float* sh_b   = (const float*)d_in[9];
    const float* sWg    = (const float*)d_in[10];
    const float* sWu    = (const float*)d_in[11];
    const float* sWd    = (const float*)d_in[12];
    const float* sgate  = (const float*)d_in[13];
    float* out = (float*)d_out;

    static int attr_done = 0;
    if (!attr_done) {
        cudaFuncSetAttribute(hm_gateup,
            cudaFuncAttributeMaxDynamicSharedMemorySize, SMEM_DYN);
        cudaFuncSetAttribute(hm_down,
            cudaFuncAttributeMaxDynamicSharedMemorySize, SMEM_DYN);
        attr_done = 1;
    }

    __half *xh, *xsh;
    cudaGetSymbolAddress((void**)&xh,  g_xh);
    cudaGetSymbolAddress((void**)&xsh, g_xsh);
    __half *hWg, *hWu, *hWd, *hsWg, *hsWu, *hsWd;
    cudaGetSymbolAddress((void**)&hWg, g_hWg);
    cudaGetSymbolAddress((void**)&hWu, g_hWu);
    cudaGetSymbolAddress((void**)&hWd, g_hWd);
    cudaGetSymbolAddress((void**)&hsWg, g_hsWg);
    cudaGetSymbolAddress((void**)&hsWu, g_hsWu);
    cudaGetSymbolAddress((void**)&hsWd, g_hsWd);

    zero_cnt_kernel<<<1, 32>>>();                                           // 1
    router_kernel<<<T_TOK, 256>>>(x, ln_g, ln_b, gate_w, bias, sh_g, sh_b,
                                  Wg, Wu, Wd, sWg, sWu, sWd);               // 2

    dim3 gu_grid(T_TOK / BM, I_DIM / 64, N_EXP + 1);
    hm_gateup<<<gu_grid, 128, SMEM_DYN>>>(xh, xsh, hWg, hWu, hsWg, hsWu);   // 3

    dim3 dn_grid(T_TOK / BM, H_DIM / 128, N_EXP + 1);
    hm_down<<<dn_grid, 128, SMEM_DYN>>>(hWd, hsWd);                         // 4 (profiled)

    combine_kernel<<<(T_TOK * H_DIM) / 256, 256>>>(out, sgate);             // 5
    aux_kernel<<<1, 256>>>(out);                                            // 6
}

// round 16
// speedup vs baseline: 1.6653x; 1.4245x over previous
#include <cuda_runtime.h>
#include <cuda_fp16.h>
#include <stdint.h>
#include <math.h>

// Problem constants
#define T_TOK 4096
#define H_DIM 1024
#define I_DIM 2048
#define N_EXP 8

// ---------------- scratch (static device globals; no allocs) ----------------
__device__ int    g_cnt[N_EXP];
__device__ int    g_tok[N_EXP][T_TOK];
__device__ float  g_wt [N_EXP][T_TOK];
__device__ int    g_slot[N_EXP][T_TOK];
__device__ __half g_hidden[(size_t)2 * T_TOK * I_DIM];
__device__ float  g_eout [(size_t)2 * T_TOK * H_DIM];
__device__ __half g_shid [(size_t)T_TOK * I_DIM];
__device__ float  g_shout[(size_t)T_TOK * H_DIM];
__device__ float  g_zsq[T_TOK];

__device__ __half g_xh  [(size_t)T_TOK * H_DIM];
__device__ __half g_xsh [(size_t)T_TOK * H_DIM];
__device__ __half g_hWg [(size_t)N_EXP * I_DIM * H_DIM];
__device__ __half g_hWu [(size_t)N_EXP * I_DIM * H_DIM];
__device__ __half g_hWd [(size_t)N_EXP * H_DIM * I_DIM];
__device__ __half g_hsWg[(size_t)I_DIM * H_DIM];
__device__ __half g_hsWu[(size_t)I_DIM * H_DIM];
__device__ __half g_hsWd[(size_t)H_DIM * I_DIM];

__device__ __forceinline__ uint32_t h2u(half2 h) { return *(uint32_t*)&h; }
__device__ __forceinline__ uint32_t smem_u32(const void* p) {
    return (uint32_t)__cvta_generic_to_shared(p);
}
__device__ __forceinline__ uint4 cvt8(float4 a, float4 b) {
    uint4 r;
    r.x = h2u(__floats2half2_rn(a.x, a.y));
    r.y = h2u(__floats2half2_rn(a.z, a.w));
    r.z = h2u(__floats2half2_rn(b.x, b.y));
    r.w = h2u(__floats2half2_rn(b.z, b.w));
    return r;
}

#define GW  (N_EXP * I_DIM * H_DIM / 8)
#define GS  (I_DIM * H_DIM / 8)
#define NWTOT (3u * GW + 3u * GS)

__global__ void zero_cnt_kernel() {
    if (threadIdx.x < N_EXP) g_cnt[threadIdx.x] = 0;
}

// ---------------- router (+ fused fp32->fp16 conversion) ----------------
__global__ void __launch_bounds__(256) router_kernel(
    const float* __restrict__ x,
    const float* __restrict__ ln_g, const float* __restrict__ ln_b,
    const float* __restrict__ gate_w, const float* __restrict__ bias,
    const float* __restrict__ sh_g, const float* __restrict__ sh_b,
    const float* __restrict__ Wg, const float* __restrict__ Wu,
    const float* __restrict__ Wd,
    const float* __restrict__ sWg, const float* __restrict__ sWu,
    const float* __restrict__ sWd)
{
    __shared__ float sx[H_DIM];
    __shared__ float sred[8], sred2[8];
    __shared__ float s_mean, s_rstd;
    __shared__ float logits[N_EXP];

    const int t   = blockIdx.x;
    const int tid = threadIdx.x;
    const float* xr = x + (size_t)t * H_DIM;

    float s = 0.f, s2 = 0.f;
#pragma unroll
    for (int i = 0; i < H_DIM / 256; i++) {
        float v = xr[tid + i * 256];
        sx[tid + i * 256] = v;
        s += v; s2 += v * v;
    }
#pragma unroll
    for (int o = 16; o; o >>= 1) {
        s  += __shfl_xor_sync(0xffffffffu, s,  o);
        s2 += __shfl_xor_sync(0xffffffffu, s2, o);
    }
    const int wid = tid >> 5, lane = tid & 31;
    if (lane == 0) { sred[wid] = s; sred2[wid] = s2; }
    __syncthreads();
    if (tid == 0) {
        float a = 0.f, b = 0.f;
        for (int i = 0; i < 8; i++) { a += sred[i]; b += sred2[i]; }
        float mean = a * (1.f / H_DIM);
        float var  = b * (1.f / H_DIM) - mean * mean;
        s_mean = mean;
        s_rstd = rsqrtf(var + 1e-5f);
    }
    __syncthreads();
    const float mean = s_mean, rstd = s_rstd;

    {
        const float* gw = gate_w + wid * H_DIM;
        float acc = 0.f;
        for (int i = lane; i < H_DIM; i += 32) {
            float hn = (sx[i] - mean) * rstd * ln_g[i] + ln_b[i];
            acc += hn * gw[i];
        }
#pragma unroll
        for (int o = 16; o; o >>= 1) acc += __shfl_xor_sync(0xffffffffu, acc, o);
        if (lane == 0) logits[wid] = acc + bias[wid];
    }

#pragma unroll
    for (int i = 0; i < H_DIM / 256; i++) {
        int idx = tid + i * 256;
        float v = sx[idx];
        g_xh [(size_t)t * H_DIM + idx] = __float2half_rn(v);
        float vn = (v - mean) * rstd * sh_g[idx] + sh_b[idx];
        g_xsh[(size_t)t * H_DIM + idx] = __float2half_rn(vn);
    }
    __syncthreads();

    if (tid == 0) {
        float mx = logits[0];
#pragma unroll
        for (int e = 1; e < N_EXP; e++) mx = fmaxf(mx, logits[e]);
        float p[N_EXP]; float se = 0.f;
#pragma unroll
        for (int e = 0; e < N_EXP; e++) { p[e] = expf(logits[e] - mx); se += p[e]; }
        float z = mx + logf(se);
        g_zsq[t] = z * z;
        int e1 = 0;
#pragma unroll
        for (int e = 1; e < N_EXP; e++) if (p[e] > p[e1]) e1 = e;
        int e2 = (e1 == 0) ? 1 : 0;
#pragma unroll
        for (int e = 0; e < N_EXP; e++) if (e != e1 && p[e] > p[e2]) e2 = e;
        float inv = 1.f / se;
        float p1 = p[e1] * inv, p2 = p[e2] * inv;
        float sm = fmaxf(p1 + p2, 1e-5f);
        int pos = atomicAdd(&g_cnt[e1], 1);
        g_tok[e1][pos] = t; g_wt[e1][pos] = p1 / sm; g_slot[e1][pos] = 2 * t;
        pos = atomicAdd(&g_cnt[e2], 1);
        g_tok[e2][pos] = t; g_wt[e2][pos] = p2 / sm; g_slot[e2][pos] = 2 * t + 1;
    }

    for (unsigned i = blockIdx.x * 256u + tid; i < NWTOT; i += 4096u * 256u) {
        const float* sp; __half* d; unsigned off;
        if (i < GW)                 { sp = Wg;  d = g_hWg;  off = i; }
        else if (i < 2u*GW)         { sp = Wu;  d = g_hWu;  off = i - GW; }
        else if (i < 3u*GW)         { sp = Wd;  d = g_hWd;  off = i - 2u*GW; }
        else if (i < 3u*GW + GS)    { sp = sWg; d = g_hsWg; off = i - 3u*GW; }
        else if (i < 3u*GW + 2u*GS) { sp = sWu; d = g_hsWu; off = i - 3u*GW - GS; }
        else                        { sp = sWd; d = g_hsWd; off = i - 3u*GW - 2u*GS; }
        float4 a = ((const float4*)sp)[2 * (size_t)off];
        float4 b = ((const float4*)sp)[2 * (size_t)off + 1];
        ((uint4*)d)[off] = cvt8(a, b);
    }
}

// ===== HMMA GEMMs: 128x128 block, 4 warps of 64x64, frag-pipelined =====
#define BM 128
#define BK 32
#define NSTAGE 5
#define TILE_PITCH 80
#define TILE_BYTES (128 * TILE_PITCH)
#define B_OFF TILE_BYTES
#define STAGE_BYTES (2 * TILE_BYTES)   // 20480
#define SMEM_DYN (NSTAGE * STAGE_BYTES + 1024)

#define MMA16816(d, a, b) \
  asm volatile("mma.sync.aligned.m16n8k16.row.col.f32.f16.f16.f32 " \
    "{%0,%1,%2,%3}, {%4,%5,%6,%7}, {%8,%9}, {%0,%1,%2,%3};" \
    : "+f"((d)[0]), "+f"((d)[1]), "+f"((d)[2]), "+f"((d)[3]) \
    : "r"((a)[0]), "r"((a)[1]), "r"((a)[2]), "r"((a)[3]), "r"((b)[0]), "r"((b)[1]))

#define LDSM4(r0, r1, r2, r3, addr) \
  asm volatile("ldmatrix.sync.aligned.m8n8.x4.shared.b16 {%0,%1,%2,%3}, [%4];" \
    : "=r"(r0), "=r"(r1), "=r"(r2), "=r"(r3) : "r"(addr))

#define CPA16(dst, src, sz) \
  asm volatile("cp.async.cg.shared.global [%0], [%1], 16, %2;" \
    :: "r"(dst), "l"(src), "r"(sz))
#define CPCOMMIT() asm volatile("cp.async.commit_group;")
#define CPWAIT(n)  asm volatile("cp.async.wait_group %0;" :: "n"(n))

#define LOADFRAG(fa, fb, stb_, soff) do { \
    const uint32_t Aw_ = (stb_) + loff + wm * TILE_PITCH + (soff); \
    const uint32_t Bw_ = (stb_) + B_OFF + loff + wn * TILE_PITCH + (soff); \
    _Pragma("unroll") \
    for (int mt = 0; mt < 4; mt++) \
        LDSM4((fa)[mt][0], (fa)[mt][1], (fa)[mt][2], (fa)[mt][3], \
              Aw_ + mt * (16 * TILE_PITCH)); \
    _Pragma("unroll") \
    for (int np = 0; np < 4; np++) { \
        uint32_t q0, q1, q2, q3; \
        LDSM4(q0, q1, q2, q3, Bw_ + np * (16 * TILE_PITCH)); \
        (fb)[2*np][0] = q0; (fb)[2*np][1] = q2; \
        (fb)[2*np+1][0] = q1; (fb)[2*np+1][1] = q3; \
    } \
} while (0)

#define MMASET(fa, fb) do { \
    _Pragma("unroll") \
    for (int mt = 0; mt < 4; mt++) \
        _Pragma("unroll") \
        for (int nt = 0; nt < 8; nt++) \
            MMA16816(acc[mt][nt], (fa)[mt], (fb)[nt]); \
} while (0)

// fused gate/up GEMM + SwiGLU.  z: 0..7 routed, 8 = shared.
// B tile rows: [0:32)=Wg n0+0..31, [32:64)=Wu n0+0..31,
//              [64:96)=Wg n0+32..63, [96:128)=Wu n0+32..63.
__global__ void __launch_bounds__(128, 2) hm_gateup(
    const __half* __restrict__ xh,  const __half* __restrict__ xsh,
    const __half* __restrict__ Wg_all, const __half* __restrict__ Wu_all,
    const __half* __restrict__ sWg, const __half* __restrict__ sWu)
{
    extern __shared__ uint8_t dsm[];
    const int e = blockIdx.z;
    const bool se = (e == N_EXP);
    const int cnt = se ? T_TOK : g_cnt[e];
    const int m0 = blockIdx.x * BM;
    if (m0 >= cnt) return;
    const int n0 = blockIdx.y * 64;

    const __half* xp = se ? xsh : xh;
    const __half* wg = se ? sWg : Wg_all + (size_t)e * I_DIM * H_DIM;
    const __half* wu = se ? sWu : Wu_all + (size_t)e * I_DIM * H_DIM;
    __half* hid = se ? g_shid : g_hidden;

    const int tid  = threadIdx.x;     // 0..127
    const int lane = tid & 31;
    const int wid  = tid >> 5;        // 0..3
    const int wm   = (wid & 1) * 64;
    const int wn   = (wid >> 1) * 64;
    const int fr   = lane >> 2;
    const int fc   = lane & 3;

    // transposed loader: thread handles seg (tid&3) of rows (tid>>2)+32k
    const int lrow4 = tid >> 2;       // 0..31
    const int lseg  = tid & 3;
    int arix[4];
    uint32_t aszm = 0;                // bit k: row k valid
#pragma unroll
    for (int k = 0; k < 4; k++) {
        int row = lrow4 + 32 * k;
        if (m0 + row < cnt) {
            arix[k] = se ? (m0 + row) : g_tok[e][m0 + row];
            aszm |= (1u << k);
        } else arix[k] = 0;
    }
    const __half* bp[4];
    bp[0] = wg + (size_t)(n0 + lrow4) * H_DIM;
    bp[1] = wu + (size_t)(n0 + lrow4) * H_DIM;
    bp[2] = wg + (size_t)(n0 + 32 + lrow4) * H_DIM;
    bp[3] = wu + (size_t)(n0 + 32 + lrow4) * H_DIM;

    const uint32_t sb = (smem_u32(dsm) + 1023) & ~1023u;
    const uint32_t adst = sb + lrow4 * TILE_PITCH + lseg * 16;
    const uint32_t bdst = adst + B_OFF;
    const uint32_t loff = (uint32_t)(((lane & 7) + ((lane >> 3) & 1) * 8) * TILE_PITCH
                                     + ((lane >> 4) & 1) * 16);

    float acc[4][8][4] = {};
    uint32_t fa0[4][4], fb0[8][2], fa1[4][4], fb1[8][2];
    const int NCH = H_DIM / BK;   // 32

#define GU_ISSUE(c, SLOT) do { \
    uint32_t st_ = (uint32_t)(SLOT) * STAGE_BYTES; \
    _Pragma("unroll") \
    for (int k = 0; k < 4; k++) { \
        uint32_t sz_ = ((aszm >> k) & 1u) << 4; \
        CPA16(adst + st_ + k * (32 * TILE_PITCH), \
              xp + (size_t)arix[k] * H_DIM + (c) * BK + lseg * 8, sz_); \
        CPA16(bdst + st_ + k * (32 * TILE_PITCH), \
              bp[k] + (c) * BK + lseg * 8, 16u); \
    } \
} while (0)

    GU_ISSUE(0, 0); CPCOMMIT();
    GU_ISSUE(1, 1); CPCOMMIT();
    GU_ISSUE(2, 2); CPCOMMIT();
    GU_ISSUE(3, 3); CPCOMMIT();

    CPWAIT(2);
    __syncthreads();
    LOADFRAG(fa0, fb0, sb, 0);        // chunk 0, slice 0 (slot 0)

    int sl = 0;
    for (int c = 0; c < NCH; c++) {
        CPWAIT(2);
        __syncthreads();
        int cc = c + 4;
        if (cc < NCH) {
            int sl2 = sl + 4; if (sl2 >= NSTAGE) sl2 -= NSTAGE;
            GU_ISSUE(cc, sl2);
        }
        CPCOMMIT();
        const uint32_t stb = sb + (uint32_t)sl * STAGE_BYTES;
        int sln = sl + 1; if (sln == NSTAGE) sln = 0;
        const uint32_t stn = sb + (uint32_t)sln * STAGE_BYTES;
        LOADFRAG(fa1, fb1, stb, 32);  // this chunk, slice 1
        MMASET(fa0, fb0);
        LOADFRAG(fa0, fb0, stn, 0);   // next chunk, slice 0
        MMASET(fa1, fb1);
        sl = sln;
    }

    // epilogue: silu(gate)*up; nt 0..3 gate, 4..7 matching up
    const int colbase = n0 + (wn >> 1);
#pragma unroll
    for (int mt = 0; mt < 4; mt++) {
#pragma unroll
        for (int i2 = 0; i2 < 2; i2++) {
            int row = wm + mt * 16 + fr + i2 * 8;
            int m = m0 + row;
            if (m >= cnt) continue;
            int orow = se ? m : g_slot[e][m];
            __half* op = hid + (size_t)orow * I_DIM + colbase;
#pragma unroll
            for (int j = 0; j < 4; j++) {
                float g0 = acc[mt][j][i2*2+0],   g1 = acc[mt][j][i2*2+1];
                float u0 = acc[mt][4+j][i2*2+0], u1 = acc[mt][4+j][i2*2+1];
                float v0 = (g0 / (1.f + expf(-g0))) * u0;
                float v1 = (g1 / (1.f + expf(-g1))) * u1;
                *(half2*)(op + j * 8 + 2 * fc) = __floats2half2_rn(v0, v1);
            }
        }
    }
}

// down GEMM (+ combine weight for routed). 128 H-cols per block.
__global__ void __launch_bounds__(128, 2) hm_down(
    const __half* __restrict__ Wd_all, const __half* __restrict__ sWd)
{
    extern __shared__ uint8_t dsm[];
    const int e = blockIdx.z;
    const bool se = (e == N_EXP);
    const int cnt = se ? T_TOK : g_cnt[e];
    const int m0 = blockIdx.x * BM;
    if (m0 >= cnt) return;
    const int n0 = blockIdx.y * 128;

    const __half* hid = se ? g_shid : g_hidden;
    const __half* wd  = se ? sWd : Wd_all + (size_t)e * H_DIM * I_DIM;

    const int tid  = threadIdx.x;
    const int lane = tid & 31;
    const int wid  = tid >> 5;
    const int wm   = (wid & 1) * 64;
    const int wn   = (wid >> 1) * 64;
    const int fr   = lane >> 2;
    const int fc   = lane & 3;

    const int lrow4 = tid >> 2;
    const int lseg  = tid & 3;
    int arix[4];
    uint32_t aszm = 0;
#pragma unroll
    for (int k = 0; k < 4; k++) {
        int row = lrow4 + 32 * k;
        if (m0 + row < cnt) {
            arix[k] = se ? (m0 + row) : g_slot[e][m0 + row];
            aszm |= (1u << k);
        } else arix[k] = 0;
    }
    const __half* bp[4];
#pragma unroll
    for (int k = 0; k < 4; k++)
        bp[k] = wd + (size_t)(n0 + lrow4 + 32 * k) * I_DIM;

    const uint32_t sb = (smem_u32(dsm) + 1023) & ~1023u;
    const uint32_t adst = sb + lrow4 * TILE_PITCH + lseg * 16;
    const uint32_t bdst = adst + B_OFF;
    const uint32_t loff = (uint32_t)(((lane & 7) + ((lane >> 3) & 1) * 8) * TILE_PITCH
                                     + ((lane >> 4) & 1) * 16);

    float acc[4][8][4] = {};
    uint32_t fa0[4][4], fb0[8][2], fa1[4][4], fb1[8][2];
    const int NCH = I_DIM / BK;   // 64

#define DN_ISSUE(c, SLOT) do { \
    uint32_t st_ = (uint32_t)(SLOT) * STAGE_BYTES; \
    _Pragma("unroll") \
    for (int k = 0; k < 4; k++) { \
        uint32_t sz_ = ((aszm >> k) & 1u) << 4; \
        CPA16(adst + st_ + k * (32 * TILE_PITCH), \
              hid + (size_t)arix[k] * I_DIM + (c) * BK + lseg * 8, sz_); \
        CPA16(bdst + st_ + k * (32 * TILE_PITCH), \
              bp[k] + (c) * BK + lseg * 8, 16u); \
    } \
} while (0)

    DN_ISSUE(0, 0); CPCOMMIT();
    DN_ISSUE(1, 1); CPCOMMIT();
    DN_ISSUE(2, 2); CPCOMMIT();
    DN_ISSUE(3, 3); CPCOMMIT();

    CPWAIT(2);
    __syncthreads();
    LOADFRAG(fa0, fb0, sb, 0);

    int sl = 0;
    for (int c = 0; c < NCH; c++) {
        CPWAIT(2);
        __syncthreads();
        int cc = c + 4;
        if (cc < NCH) {
            int sl2 = sl + 4; if (sl2 >= NSTAGE) sl2 -= NSTAGE;
            DN_ISSUE(cc, sl2);
        }
        CPCOMMIT();
        const uint32_t stb = sb + (uint32_t)sl * STAGE_BYTES;
        int sln = sl + 1; if (sln == NSTAGE) sln = 0;
        const uint32_t stn = sb + (uint32_t)sln * STAGE_BYTES;
        LOADFRAG(fa1, fb1, stb, 32);
        MMASET(fa0, fb0);
        LOADFRAG(fa0, fb0, stn, 0);
        MMASET(fa1, fb1);
        sl = sln;
    }

#pragma unroll
    for (int mt = 0; mt < 4; mt++) {
#pragma unroll
        for (int i2 = 0; i2 < 2; i2++) {
            int row = wm + mt * 16 + fr + i2 * 8;
            int m = m0 + row;
            if (m >= cnt) continue;
            if (se) {
                float* op = g_shout + (size_t)m * H_DIM + n0 + wn;
#pragma unroll
                for (int nt = 0; nt < 8; nt++) {
                    float2 v;
                    v.x = acc[mt][nt][i2*2+0];
                    v.y = acc[mt][nt][i2*2+1];
                    *(float2*)(op + nt * 8 + 2 * fc) = v;
                }
            } else {
                int orow = g_slot[e][m];
                float w  = g_wt[e][m];
                float* op = g_eout + (size_t)orow * H_DIM + n0 + wn;
#pragma unroll
                for (int nt = 0; nt < 8; nt++) {
                    float2 v;
                    v.x = acc[mt][nt][i2*2+0] * w;
                    v.y = acc[mt][nt][i2*2+1] * w;
                    *(float2*)(op + nt * 8 + 2 * fc) = v;
                }
            }
        }
    }
}

// ---------------- combine ----------------
__global__ void __launch_bounds__(256) combine_kernel(
    float* __restrict__ out, const float* __restrict__ shared_gate)
{
    const int idx = blockIdx.x * 256 + threadIdx.x;
    const float sig = 1.f / (1.f + expf(-shared_gate[0]));
    const int t = idx >> 10;
    const int h = idx & (H_DIM - 1);
    out[idx] = g_eout[(size_t)(2 * t) * H_DIM + h]
             + g_eout[(size_t)(2 * t + 1) * H_DIM + h]
             + g_shout[idx] * sig;
}

// ---------------- aux z-loss ----------------
__global__ void __launch_bounds__(256) aux_kernel(float* __restrict__ out)
{
    __shared__ float red[256];
    const int tid = threadIdx.x;
    float s = 0.f;
    for (int i = tid; i < T_TOK; i += 256) s += g_zsq[i];
    red[tid] = s;
    __syncthreads();
    for (int o = 128; o; o >>= 1) {
        if (tid < o) red[tid] += red[tid + o];
        __syncthreads();
    }
    if (tid == 0) out[(size_t)T_TOK * H_DIM] = red[0] * (1e-4f / T_TOK);
}

// ---------------- launch ----------------
extern "C" void kernel_launch(void* const* d_in, const int* in_sizes, int n_in,
                              void* d_out, int out_size)
{
    const float* x      = (const float*)d_in[0];
    const float* ln_g   = (const float*)d_in[1];
    const float* ln_b   = (const float*)d_in[2];
    const float* gate_w = (const float*)d_in[3];
    const float* bias   = (const float*)d_in[4];
    const float* Wg     = (const float*)d_in[5];
    const float* Wu     = (const float*)d_in[6];
    const float* Wd     = (const float*)d_in[7];
    const float* sh_g   = (const float*)d_in[8];
    const float* sh_b   = (const float*)d_in[9];
    const float* sWg    = (const float*)d_in[10];
    const float* sWu    = (const float*)d_in[11];
    const float* sWd    = (const float*)d_in[12];
    const float* sgate  = (const float*)d_in[13];
    float* out = (float*)d_out;

    static int attr_done = 0;
    if (!attr_done) {
        cudaFuncSetAttribute(hm_gateup,
            cudaFuncAttributeMaxDynamicSharedMemorySize, SMEM_DYN);
        cudaFuncSetAttribute(hm_down,
            cudaFuncAttributeMaxDynamicSharedMemorySize, SMEM_DYN);
        attr_done = 1;
    }

    __half *xh, *xsh;
    cudaGetSymbolAddress((void**)&xh,  g_xh);
    cudaGetSymbolAddress((void**)&xsh, g_xsh);
    __half *hWg, *hWu, *hWd, *hsWg, *hsWu, *hsWd;
    cudaGetSymbolAddress((void**)&hWg, g_hWg);
    cudaGetSymbolAddress((void**)&hWu, g_hWu);
    cudaGetSymbolAddress((void**)&hWd, g_hWd);
    cudaGetSymbolAddress((void**)&hsWg, g_hsWg);
    cudaGetSymbolAddress((void**)&hsWu, g_hsWu);
    cudaGetSymbolAddress((void**)&hsWd, g_hsWd);

    zero_cnt_kernel<<<1, 32>>>();                                           // 1
    router_kernel<<<T_TOK, 256>>>(x, ln_g, ln_b, gate_w, bias, sh_g, sh_b,
                                  Wg, Wu, Wd, sWg, sWu, sWd);               // 2

    dim3 gu_grid(T_TOK / BM, I_DIM / 64, N_EXP + 1);
    hm_gateup<<<gu_grid, 128, SMEM_DYN>>>(xh, xsh, hWg, hWu, hsWg, hsWu);   // 3

    dim3 dn_grid(T_TOK / BM, H_DIM / 128, N_EXP + 1);
    hm_down<<<dn_grid, 128, SMEM_DYN>>>(hWd, hsWd);                         // 4 (profiled)

    combine_kernel<<<(T_TOK * H_DIM) / 256, 256>>>(out, sgate);             // 5
    aux_kernel<<<1, 256>>>(out);                                            // 6
}